// round 5
// baseline (speedup 1.0000x reference)
#include <cuda_runtime.h>
#include <cstdint>

// Problem constants
#define BQ   16
#define TT   1024
#define CC   512
#define MTOT (BQ * TT)      // 16384 rows (b,t)
#define C2   (2 * CC)       // 1024

// ---------------- scratch (device globals; no allocation allowed) -----------
__device__ float g_xn[(size_t)MTOT * CC];       // LN output (tf32-rounded)
__device__ float g_h1[(size_t)MTOT * C2];       // GEMM1+SiLU output (tf32-rounded)
__device__ float g_hc[(size_t)MTOT * C2];       // conv output (fp32)
__device__ float g_h2[(size_t)MTOT * CC];       // GLU+BN output (tf32-rounded)
__device__ float g_w1r[(size_t)C2 * CC];        // tf32-rounded weights
__device__ float g_w2r[(size_t)5 * C2 * C2];
__device__ float g_w3r[(size_t)CC * CC];

// ---------------- helpers ---------------------------------------------------
__device__ __forceinline__ float tf32r(float x) {
    uint32_t u;
    asm("cvt.rna.tf32.f32 %0, %1;" : "=r"(u) : "f"(x));
    return __uint_as_float(u);
}

__device__ __forceinline__ void mma8(float (&d)[4], const uint32_t (&a)[4], const uint32_t (&b)[2]) {
    asm volatile(
        "mma.sync.aligned.m16n8k8.row.col.f32.tf32.tf32.f32 "
        "{%0,%1,%2,%3}, {%4,%5,%6,%7}, {%8,%9}, {%0,%1,%2,%3};\n"
        : "+f"(d[0]), "+f"(d[1]), "+f"(d[2]), "+f"(d[3])
        : "r"(a[0]), "r"(a[1]), "r"(a[2]), "r"(a[3]),
          "r"(b[0]), "r"(b[1]));
}

__device__ __forceinline__ void cpa16(uint32_t dst, const float* src) {
    asm volatile("cp.async.cg.shared.global [%0], [%1], 16;\n" :: "r"(dst), "l"(src));
}
__device__ __forceinline__ void cpa16p(uint32_t dst, const float* src, bool pred) {
    int sz = pred ? 16 : 0;
    asm volatile("cp.async.cg.shared.global [%0], [%1], 16, %2;\n" :: "r"(dst), "l"(src), "r"(sz));
}
__device__ __forceinline__ void cp_commit() { asm volatile("cp.async.commit_group;\n"); }
__device__ __forceinline__ void cp_wait1() { asm volatile("cp.async.wait_group 1;\n"); }

__device__ __forceinline__ float fsigmoid(float v) { return 1.f / (1.f + __expf(-v)); }

// ---------------- 0) tf32-round weight copies --------------------------------
__global__ void round_copy(const float* __restrict__ src, float* __restrict__ dst, int n4) {
    int i = blockIdx.x * blockDim.x + threadIdx.x;
    if (i < n4) {
        float4 v = ((const float4*)src)[i];
        ((float4*)dst)[i] = make_float4(tf32r(v.x), tf32r(v.y), tf32r(v.z), tf32r(v.w));
    }
}

// ---------------- 1) LayerNorm (stores tf32-rounded) -------------------------
__global__ void ln_kernel(const float* __restrict__ x,
                          const float* __restrict__ lg,
                          const float* __restrict__ lb) {
    int row = blockIdx.x;
    const float2* xin = (const float2*)(x + (size_t)row * CC);
    float2 v = xin[threadIdx.x];
    float s = v.x + v.y;
    float q = v.x * v.x + v.y * v.y;
    #pragma unroll
    for (int o = 16; o; o >>= 1) {
        s += __shfl_xor_sync(0xffffffffu, s, o);
        q += __shfl_xor_sync(0xffffffffu, q, o);
    }
    __shared__ float ss[8], sq[8];
    __shared__ float mu_s, rs_s;
    int w = threadIdx.x >> 5, l = threadIdx.x & 31;
    if (l == 0) { ss[w] = s; sq[w] = q; }
    __syncthreads();
    if (threadIdx.x == 0) {
        float S = 0.f, Q = 0.f;
        #pragma unroll
        for (int i = 0; i < 8; i++) { S += ss[i]; Q += sq[i]; }
        float mu = S * (1.f / CC);
        float var = Q * (1.f / CC) - mu * mu;
        mu_s = mu;
        rs_s = rsqrtf(var + 1e-5f);
    }
    __syncthreads();
    float mu = mu_s, rs = rs_s;
    int c = threadIdx.x * 2;
    float2 o;
    o.x = tf32r((v.x - mu) * rs * lg[c]     + lb[c]);
    o.y = tf32r((v.y - mu) * rs * lg[c + 1] + lb[c + 1]);
    ((float2*)(g_xn + (size_t)row * CC))[threadIdx.x] = o;
}

// ---------------- 2/5) GEMM:  C = act(A @ W^T + bias) -----------------------
// Tile 128x128xK32, 8 warps (2x4), warp tile 64x32. 3-stage cp.async pipeline.
// All MMA operands arrive in smem ALREADY tf32-rounded (producers round).
// MODE 0: A = g_xn, C = g_h1 (ACT=silu, store rounded). MODE 1: A = g_h2 -> out.
template <int ACT, int N, int MODE, int KD>
__global__ __launch_bounds__(256)
void gemm_wt(const float* __restrict__ W, const float* __restrict__ bias,
             float* __restrict__ outParam) {
    extern __shared__ float sm[];
    constexpr int ASZ = 128 * 36;
    constexpr int BSZ = 128 * 36;
    float* AsB = sm;
    float* BsB = sm + 3 * ASZ;
    constexpr int KT = KD / 32;

    const float* A    = (MODE == 0) ? g_xn : g_h2;
    float*       Cout = (MODE == 0) ? g_h1 : outParam;

    const int m0 = blockIdx.x * 128, n0 = blockIdx.y * 128;
    const int tid = threadIdx.x;
    const int lane = tid & 31, warp = tid >> 5;
    const int wm = warp & 1, wn = warp >> 1;      // 2x4 warp grid, 64x32 / warp
    const int g = lane >> 2, t = lane & 3;
    const int ar = tid >> 3, ac = (tid & 7) * 4;

    auto stage = [&](int s) {
        float* a = AsB + (s % 3) * ASZ;
        float* b = BsB + (s % 3) * BSZ;
        const float* Ap = A + (size_t)(m0 + ar) * KD + s * 32 + ac;
        #pragma unroll
        for (int i = 0; i < 4; i++) {
            uint32_t d = (uint32_t)__cvta_generic_to_shared(a + (ar + i * 32) * 36 + ac);
            cpa16(d, Ap + (size_t)(i * 32) * KD);
        }
        #pragma unroll
        for (int j = 0; j < 4; j++) {
            int n  = j * 32 + (tid >> 3);
            int kc = (tid & 7) * 4;
            uint32_t d = (uint32_t)__cvta_generic_to_shared(b + n * 36 + kc);
            cpa16(d, W + (size_t)(n0 + n) * KD + s * 32 + kc);
        }
        cp_commit();
    };

    float acc[4][4][4];
    #pragma unroll
    for (int mi = 0; mi < 4; mi++)
        #pragma unroll
        for (int ni = 0; ni < 4; ni++)
            #pragma unroll
            for (int j = 0; j < 4; j++) acc[mi][ni][j] = 0.f;

    auto comp = [&](int s) {
        const uint32_t* a = (const uint32_t*)(AsB + (s % 3) * ASZ);
        const uint32_t* b = (const uint32_t*)(BsB + (s % 3) * BSZ);
        #pragma unroll
        for (int ks = 0; ks < 4; ks++) {
            const int kb = ks * 8;
            uint32_t af[4][4];
            #pragma unroll
            for (int mi = 0; mi < 4; mi++) {
                int r0 = wm * 64 + mi * 16 + g;
                af[mi][0] = a[r0 * 36 + kb + t];
                af[mi][1] = a[(r0 + 8) * 36 + kb + t];
                af[mi][2] = a[r0 * 36 + kb + t + 4];
                af[mi][3] = a[(r0 + 8) * 36 + kb + t + 4];
            }
            uint32_t bf[4][2];
            #pragma unroll
            for (int ni = 0; ni < 4; ni++) {
                int c0 = wn * 32 + ni * 8 + g;
                bf[ni][0] = b[c0 * 36 + kb + t];
                bf[ni][1] = b[c0 * 36 + kb + t + 4];
            }
            #pragma unroll
            for (int mi = 0; mi < 4; mi++)
                #pragma unroll
                for (int ni = 0; ni < 4; ni++)
                    mma8(acc[mi][ni], af[mi], bf[ni]);
        }
    };

    stage(0);
    stage(1);
    #pragma unroll 1
    for (int kt = 0; kt < KT; ++kt) {
        cp_wait1();
        __syncthreads();
        if (kt + 2 < KT) stage(kt + 2);
        comp(kt);
    }

    #pragma unroll
    for (int mi = 0; mi < 4; mi++) {
        int r0 = m0 + wm * 64 + mi * 16 + g;
        #pragma unroll
        for (int ni = 0; ni < 4; ni++) {
            int c0 = n0 + wn * 32 + ni * 8 + t * 2;
            float2 v0, v1;
            v0.x = acc[mi][ni][0] + bias[c0];
            v0.y = acc[mi][ni][1] + bias[c0 + 1];
            v1.x = acc[mi][ni][2] + bias[c0];
            v1.y = acc[mi][ni][3] + bias[c0 + 1];
            if (ACT == 1) {
                v0.x = tf32r(v0.x * fsigmoid(v0.x));
                v0.y = tf32r(v0.y * fsigmoid(v0.y));
                v1.x = tf32r(v1.x * fsigmoid(v1.x));
                v1.y = tf32r(v1.y * fsigmoid(v1.y));
            }
            *(float2*)(Cout + (size_t)r0 * N + c0)       = v0;
            *(float2*)(Cout + (size_t)(r0 + 8) * N + c0) = v1;
        }
    }
}

// ---------------- 3) Conv1d (K=5) as 5 accumulated GEMMs ---------------------
// out[m,o] = sum_{kc} sum_i g_h1[m + (kc-2), i] * w2[kc, i, o] + b2[o]
__global__ __launch_bounds__(256)
void conv_gemm(const float* __restrict__ W2, const float* __restrict__ b2) {
    extern __shared__ float sm[];
    constexpr int ASZ = 128 * 36;     // A tile [row][k] stride 36
    constexpr int BSZ = 32 * 136;     // B tile [k][n]  stride 136
    float* AsB = sm;
    float* BsB = sm + 3 * ASZ;
    constexpr int NIT = 160;          // 32 K-tiles x 5 taps

    const int m0 = blockIdx.x * 128, n0 = blockIdx.y * 128;
    const int bb = m0 >> 10, t0 = m0 & 1023;
    const int tid = threadIdx.x;
    const int lane = tid & 31, warp = tid >> 5;
    const int wm = warp & 1, wn = warp >> 1;
    const int g = lane >> 2, t = lane & 3;
    const int ar = tid >> 3, ac = (tid & 7) * 4;

    auto stage = [&](int s) {
        int kt = s / 5;
        int kc = s - kt * 5;
        float* a = AsB + (s % 3) * ASZ;
        float* b = BsB + (s % 3) * BSZ;
        int shift = kc - 2;
        const float* Abase = g_h1 + (size_t)(bb * TT) * C2 + kt * 32 + ac;
        #pragma unroll
        for (int i = 0; i < 4; i++) {
            int trow = t0 + ar + i * 32 + shift;
            bool ok = (trow >= 0) && (trow < TT);
            int srow = ok ? trow : 0;
            uint32_t d = (uint32_t)__cvta_generic_to_shared(a + (ar + i * 32) * 36 + ac);
            cpa16p(d, Abase + (size_t)srow * C2, ok);
        }
        const float* Wk = W2 + (size_t)kc * C2 * C2 + (size_t)(kt * 32) * C2 + n0;
        #pragma unroll
        for (int j = 0; j < 4; j++) {
            int k  = j * 8 + (tid >> 5);
            int n4 = (tid & 31) * 4;
            uint32_t d = (uint32_t)__cvta_generic_to_shared(b + k * 136 + n4);
            cpa16(d, Wk + (size_t)k * C2 + n4);
        }
        cp_commit();
    };

    float acc[4][4][4];
    #pragma unroll
    for (int mi = 0; mi < 4; mi++)
        #pragma unroll
        for (int ni = 0; ni < 4; ni++)
            #pragma unroll
            for (int j = 0; j < 4; j++) acc[mi][ni][j] = 0.f;

    auto comp = [&](int s) {
        const uint32_t* a = (const uint32_t*)(AsB + (s % 3) * ASZ);
        const uint32_t* b = (const uint32_t*)(BsB + (s % 3) * BSZ);
        #pragma unroll
        for (int ks = 0; ks < 4; ks++) {
            const int kb = ks * 8;
            uint32_t af[4][4];
            #pragma unroll
            for (int mi = 0; mi < 4; mi++) {
                int r0 = wm * 64 + mi * 16 + g;
                af[mi][0] = a[r0 * 36 + kb + t];
                af[mi][1] = a[(r0 + 8) * 36 + kb + t];
                af[mi][2] = a[r0 * 36 + kb + t + 4];
                af[mi][3] = a[(r0 + 8) * 36 + kb + t + 4];
            }
            uint32_t bf[4][2];
            #pragma unroll
            for (int ni = 0; ni < 4; ni++) {
                int c0 = wn * 32 + ni * 8 + g;
                bf[ni][0] = b[(kb + t) * 136 + c0];
                bf[ni][1] = b[(kb + t + 4) * 136 + c0];
            }
            #pragma unroll
            for (int mi = 0; mi < 4; mi++)
                #pragma unroll
                for (int ni = 0; ni < 4; ni++)
                    mma8(acc[mi][ni], af[mi], bf[ni]);
        }
    };

    stage(0);
    stage(1);
    #pragma unroll 1
    for (int s = 0; s < NIT; ++s) {
        cp_wait1();
        __syncthreads();
        if (s + 2 < NIT) stage(s + 2);
        comp(s);
    }

    #pragma unroll
    for (int mi = 0; mi < 4; mi++) {
        int r0 = m0 + wm * 64 + mi * 16 + g;
        #pragma unroll
        for (int ni = 0; ni < 4; ni++) {
            int c0 = n0 + wn * 32 + ni * 8 + t * 2;
            float2 v0, v1;
            v0.x = acc[mi][ni][0] + b2[c0];
            v0.y = acc[mi][ni][1] + b2[c0 + 1];
            v1.x = acc[mi][ni][2] + b2[c0];
            v1.y = acc[mi][ni][3] + b2[c0 + 1];
            *(float2*)(g_hc + (size_t)r0 * C2 + c0)       = v0;
            *(float2*)(g_hc + (size_t)(r0 + 8) * C2 + c0) = v1;
        }
    }
}

// ---------------- 4) GLU + BatchNorm (stores tf32-rounded) -------------------
__global__ void glu_bn(const float* __restrict__ bg, const float* __restrict__ bb_,
                       const float* __restrict__ bm, const float* __restrict__ bv) {
    int p = blockIdx.x * blockDim.x + threadIdx.x;   // float4 index
    int m = p >> 7;                                  // 128 float4 per row
    int c4 = (p & 127) * 4;
    float4 a  = *(const float4*)(g_hc + (size_t)m * C2 + c4);
    float4 gg = *(const float4*)(g_hc + (size_t)m * C2 + CC + c4);
    float4 o;
    {
        float s = bg[c4] * rsqrtf(bv[c4] + 1e-5f);
        o.x = tf32r((a.x * fsigmoid(gg.x) - bm[c4]) * s + bb_[c4]);
    }
    {
        float s = bg[c4 + 1] * rsqrtf(bv[c4 + 1] + 1e-5f);
        o.y = tf32r((a.y * fsigmoid(gg.y) - bm[c4 + 1]) * s + bb_[c4 + 1]);
    }
    {
        float s = bg[c4 + 2] * rsqrtf(bv[c4 + 2] + 1e-5f);
        o.z = tf32r((a.z * fsigmoid(gg.z) - bm[c4 + 2]) * s + bb_[c4 + 2]);
    }
    {
        float s = bg[c4 + 3] * rsqrtf(bv[c4 + 3] + 1e-5f);
        o.w = tf32r((a.w * fsigmoid(gg.w) - bm[c4 + 3]) * s + bb_[c4 + 3]);
    }
    *(float4*)(g_h2 + (size_t)m * CC + c4) = o;
}

// ---------------- launch -----------------------------------------------------
extern "C" void kernel_launch(void* const* d_in, const int* in_sizes, int n_in,
                              void* d_out, int out_size) {
    const float* x     = (const float*)d_in[0];
    const float* ln_g  = (const float*)d_in[1];
    const float* ln_b  = (const float*)d_in[2];
    const float* w1    = (const float*)d_in[3];
    const float* b1    = (const float*)d_in[4];
    const float* w2    = (const float*)d_in[5];
    const float* b2    = (const float*)d_in[6];
    const float* bn_g  = (const float*)d_in[7];
    const float* bn_b  = (const float*)d_in[8];
    const float* bn_m  = (const float*)d_in[9];
    const float* bn_v  = (const float*)d_in[10];
    const float* w3    = (const float*)d_in[11];
    const float* b3    = (const float*)d_in[12];
    float* out = (float*)d_out;

    const int smem_gemm = 3 * (128 * 36 + 128 * 36) * 4;   // 110592
    const int smem_conv = 3 * (128 * 36 + 32 * 136) * 4;   // 107520
    cudaFuncSetAttribute(gemm_wt<1, C2, 0, CC>,
                         cudaFuncAttributeMaxDynamicSharedMemorySize, smem_gemm);
    cudaFuncSetAttribute(gemm_wt<0, CC, 1, CC>,
                         cudaFuncAttributeMaxDynamicSharedMemorySize, smem_gemm);
    cudaFuncSetAttribute(conv_gemm,
                         cudaFuncAttributeMaxDynamicSharedMemorySize, smem_conv);

    // Resolve device-global weight buffers (host side, no allocation)
    float *w1r, *w2r, *w3r;
    cudaGetSymbolAddress((void**)&w1r, g_w1r);
    cudaGetSymbolAddress((void**)&w2r, g_w2r);
    cudaGetSymbolAddress((void**)&w3r, g_w3r);

    round_copy<<<(C2 * CC / 4 + 255) / 256, 256>>>(w1, w1r, C2 * CC / 4);
    round_copy<<<(5 * C2 * C2 / 4 + 255) / 256, 256>>>(w2, w2r, 5 * C2 * C2 / 4);
    round_copy<<<(CC * CC / 4 + 255) / 256, 256>>>(w3, w3r, CC * CC / 4);

    ln_kernel<<<MTOT, 256>>>(x, ln_g, ln_b);
    gemm_wt<1, C2, 0, CC><<<dim3(MTOT / 128, C2 / 128), 256, smem_gemm>>>(w1r, b1, nullptr);
    conv_gemm<<<dim3(MTOT / 128, C2 / 128), 256, smem_conv>>>(w2r, b2);
    glu_bn<<<(MTOT * CC / 4) / 256, 256>>>(bn_g, bn_b, bn_m, bn_v);
    gemm_wt<0, CC, 1, CC><<<dim3(MTOT / 128, CC / 128), 256, smem_gemm>>>(w3r, b3, out);
}

// round 6
// speedup vs baseline: 1.5335x; 1.5335x over previous
#include <cuda_runtime.h>
#include <cstdint>

// Problem constants
#define BQ   16
#define TT   1024
#define CC   512
#define MTOT (BQ * TT)      // 16384 rows (b,t)
#define C2   (2 * CC)       // 1024

// ---------------- scratch (device globals; no allocation allowed) -----------
__device__ float g_xn[(size_t)MTOT * CC];       // LN output (tf32-rounded)
__device__ float g_h1[(size_t)MTOT * C2];       // GEMM1+SiLU output (tf32-rounded)
__device__ float g_hc[(size_t)MTOT * C2];       // conv output (fp32)
__device__ float g_h2[(size_t)MTOT * CC];       // GLU+BN output (tf32-rounded)
__device__ float g_w1r[(size_t)C2 * CC];        // tf32-rounded weights
__device__ float g_w2r[(size_t)5 * C2 * C2];
__device__ float g_w3r[(size_t)CC * CC];

// ---------------- helpers ---------------------------------------------------
__device__ __forceinline__ float tf32r(float x) {
    uint32_t u;
    asm("cvt.rna.tf32.f32 %0, %1;" : "=r"(u) : "f"(x));
    return __uint_as_float(u);
}

__device__ __forceinline__ void mma8(float (&d)[4], const uint32_t (&a)[4], const uint32_t (&b)[2]) {
    asm volatile(
        "mma.sync.aligned.m16n8k8.row.col.f32.tf32.tf32.f32 "
        "{%0,%1,%2,%3}, {%4,%5,%6,%7}, {%8,%9}, {%0,%1,%2,%3};\n"
        : "+f"(d[0]), "+f"(d[1]), "+f"(d[2]), "+f"(d[3])
        : "r"(a[0]), "r"(a[1]), "r"(a[2]), "r"(a[3]),
          "r"(b[0]), "r"(b[1]));
}

__device__ __forceinline__ void cpa16(uint32_t dst, const float* src) {
    asm volatile("cp.async.cg.shared.global [%0], [%1], 16;\n" :: "r"(dst), "l"(src));
}
__device__ __forceinline__ void cpa16p(uint32_t dst, const float* src, bool pred) {
    int sz = pred ? 16 : 0;
    asm volatile("cp.async.cg.shared.global [%0], [%1], 16, %2;\n" :: "r"(dst), "l"(src), "r"(sz));
}
__device__ __forceinline__ void cp_commit() { asm volatile("cp.async.commit_group;\n"); }
__device__ __forceinline__ void cp_wait1() { asm volatile("cp.async.wait_group 1;\n"); }

__device__ __forceinline__ float fsigmoid(float v) { return 1.f / (1.f + __expf(-v)); }

// ---------------- 0) tf32-round weight copies --------------------------------
__global__ void round_copy(const float* __restrict__ src, float* __restrict__ dst, int n4) {
    int i = blockIdx.x * blockDim.x + threadIdx.x;
    if (i < n4) {
        float4 v = ((const float4*)src)[i];
        ((float4*)dst)[i] = make_float4(tf32r(v.x), tf32r(v.y), tf32r(v.z), tf32r(v.w));
    }
}

// ---------------- 1) LayerNorm (stores tf32-rounded) -------------------------
__global__ void ln_kernel(const float* __restrict__ x,
                          const float* __restrict__ lg,
                          const float* __restrict__ lb) {
    int row = blockIdx.x;
    const float2* xin = (const float2*)(x + (size_t)row * CC);
    float2 v = xin[threadIdx.x];
    float s = v.x + v.y;
    float q = v.x * v.x + v.y * v.y;
    #pragma unroll
    for (int o = 16; o; o >>= 1) {
        s += __shfl_xor_sync(0xffffffffu, s, o);
        q += __shfl_xor_sync(0xffffffffu, q, o);
    }
    __shared__ float ss[8], sq[8];
    __shared__ float mu_s, rs_s;
    int w = threadIdx.x >> 5, l = threadIdx.x & 31;
    if (l == 0) { ss[w] = s; sq[w] = q; }
    __syncthreads();
    if (threadIdx.x == 0) {
        float S = 0.f, Q = 0.f;
        #pragma unroll
        for (int i = 0; i < 8; i++) { S += ss[i]; Q += sq[i]; }
        float mu = S * (1.f / CC);
        float var = Q * (1.f / CC) - mu * mu;
        mu_s = mu;
        rs_s = rsqrtf(var + 1e-5f);
    }
    __syncthreads();
    float mu = mu_s, rs = rs_s;
    int c = threadIdx.x * 2;
    float2 o;
    o.x = tf32r((v.x - mu) * rs * lg[c]     + lb[c]);
    o.y = tf32r((v.y - mu) * rs * lg[c + 1] + lb[c + 1]);
    ((float2*)(g_xn + (size_t)row * CC))[threadIdx.x] = o;
}

// ---------------- 2/5) GEMM:  C = act(A @ W^T + bias) -----------------------
// Tile 128x128xK32, 8 warps (2x4), warp tile 64x32. 3-stage cp.async pipeline.
// All MMA operands arrive in smem ALREADY tf32-rounded (producers round).
// __launch_bounds__(256,2): cap regs at 128 so 2 CTAs/SM co-reside (smem 110KB*2 fits).
// MODE 0: A = g_xn, C = g_h1 (ACT=silu, store rounded). MODE 1: A = g_h2 -> out.
template <int ACT, int N, int MODE, int KD>
__global__ __launch_bounds__(256, 2)
void gemm_wt(const float* __restrict__ W, const float* __restrict__ bias,
             float* __restrict__ outParam) {
    extern __shared__ float sm[];
    constexpr int ASZ = 128 * 36;
    constexpr int BSZ = 128 * 36;
    float* AsB = sm;
    float* BsB = sm + 3 * ASZ;
    constexpr int KT = KD / 32;

    const float* A    = (MODE == 0) ? g_xn : g_h2;
    float*       Cout = (MODE == 0) ? g_h1 : outParam;

    const int m0 = blockIdx.x * 128, n0 = blockIdx.y * 128;
    const int tid = threadIdx.x;
    const int lane = tid & 31, warp = tid >> 5;
    const int wm = warp & 1, wn = warp >> 1;      // 2x4 warp grid, 64x32 / warp
    const int g = lane >> 2, t = lane & 3;
    const int ar = tid >> 3, ac = (tid & 7) * 4;

    auto stage = [&](int s) {
        float* a = AsB + (s % 3) * ASZ;
        float* b = BsB + (s % 3) * BSZ;
        const float* Ap = A + (size_t)(m0 + ar) * KD + s * 32 + ac;
        #pragma unroll
        for (int i = 0; i < 4; i++) {
            uint32_t d = (uint32_t)__cvta_generic_to_shared(a + (ar + i * 32) * 36 + ac);
            cpa16(d, Ap + (size_t)(i * 32) * KD);
        }
        #pragma unroll
        for (int j = 0; j < 4; j++) {
            int n  = j * 32 + (tid >> 3);
            int kc = (tid & 7) * 4;
            uint32_t d = (uint32_t)__cvta_generic_to_shared(b + n * 36 + kc);
            cpa16(d, W + (size_t)(n0 + n) * KD + s * 32 + kc);
        }
        cp_commit();
    };

    float acc[4][4][4];
    #pragma unroll
    for (int mi = 0; mi < 4; mi++)
        #pragma unroll
        for (int ni = 0; ni < 4; ni++)
            #pragma unroll
            for (int j = 0; j < 4; j++) acc[mi][ni][j] = 0.f;

    auto comp = [&](int s) {
        const uint32_t* a = (const uint32_t*)(AsB + (s % 3) * ASZ);
        const uint32_t* b = (const uint32_t*)(BsB + (s % 3) * BSZ);
        #pragma unroll
        for (int ks = 0; ks < 4; ks++) {
            const int kb = ks * 8;
            uint32_t af[4][4];
            #pragma unroll
            for (int mi = 0; mi < 4; mi++) {
                int r0 = wm * 64 + mi * 16 + g;
                af[mi][0] = a[r0 * 36 + kb + t];
                af[mi][1] = a[(r0 + 8) * 36 + kb + t];
                af[mi][2] = a[r0 * 36 + kb + t + 4];
                af[mi][3] = a[(r0 + 8) * 36 + kb + t + 4];
            }
            uint32_t bf[4][2];
            #pragma unroll
            for (int ni = 0; ni < 4; ni++) {
                int c0 = wn * 32 + ni * 8 + g;
                bf[ni][0] = b[c0 * 36 + kb + t];
                bf[ni][1] = b[c0 * 36 + kb + t + 4];
            }
            #pragma unroll
            for (int mi = 0; mi < 4; mi++)
                #pragma unroll
                for (int ni = 0; ni < 4; ni++)
                    mma8(acc[mi][ni], af[mi], bf[ni]);
        }
    };

    stage(0);
    stage(1);
    #pragma unroll 1
    for (int kt = 0; kt < KT; ++kt) {
        cp_wait1();
        __syncthreads();
        if (kt + 2 < KT) stage(kt + 2);
        comp(kt);
    }

    #pragma unroll
    for (int mi = 0; mi < 4; mi++) {
        int r0 = m0 + wm * 64 + mi * 16 + g;
        #pragma unroll
        for (int ni = 0; ni < 4; ni++) {
            int c0 = n0 + wn * 32 + ni * 8 + t * 2;
            float2 v0, v1;
            v0.x = acc[mi][ni][0] + bias[c0];
            v0.y = acc[mi][ni][1] + bias[c0 + 1];
            v1.x = acc[mi][ni][2] + bias[c0];
            v1.y = acc[mi][ni][3] + bias[c0 + 1];
            if (ACT == 1) {
                v0.x = tf32r(v0.x * fsigmoid(v0.x));
                v0.y = tf32r(v0.y * fsigmoid(v0.y));
                v1.x = tf32r(v1.x * fsigmoid(v1.x));
                v1.y = tf32r(v1.y * fsigmoid(v1.y));
            }
            *(float2*)(Cout + (size_t)r0 * N + c0)       = v0;
            *(float2*)(Cout + (size_t)(r0 + 8) * N + c0) = v1;
        }
    }
}

// ---------------- 3) Conv1d (K=5) as 5 accumulated GEMMs ---------------------
// out[m,o] = sum_{kc} sum_i g_h1[m + (kc-2), i] * w2[kc, i, o] + b2[o]
__global__ __launch_bounds__(256, 2)
void conv_gemm(const float* __restrict__ W2, const float* __restrict__ b2) {
    extern __shared__ float sm[];
    constexpr int ASZ = 128 * 36;     // A tile [row][k] stride 36
    constexpr int BSZ = 32 * 136;     // B tile [k][n]  stride 136
    float* AsB = sm;
    float* BsB = sm + 3 * ASZ;
    constexpr int NIT = 160;          // 32 K-tiles x 5 taps

    const int m0 = blockIdx.x * 128, n0 = blockIdx.y * 128;
    const int bb = m0 >> 10, t0 = m0 & 1023;
    const int tid = threadIdx.x;
    const int lane = tid & 31, warp = tid >> 5;
    const int wm = warp & 1, wn = warp >> 1;
    const int g = lane >> 2, t = lane & 3;
    const int ar = tid >> 3, ac = (tid & 7) * 4;

    auto stage = [&](int s) {
        int kt = s / 5;
        int kc = s - kt * 5;
        float* a = AsB + (s % 3) * ASZ;
        float* b = BsB + (s % 3) * BSZ;
        int shift = kc - 2;
        const float* Abase = g_h1 + (size_t)(bb * TT) * C2 + kt * 32 + ac;
        #pragma unroll
        for (int i = 0; i < 4; i++) {
            int trow = t0 + ar + i * 32 + shift;
            bool ok = (trow >= 0) && (trow < TT);
            int srow = ok ? trow : 0;
            uint32_t d = (uint32_t)__cvta_generic_to_shared(a + (ar + i * 32) * 36 + ac);
            cpa16p(d, Abase + (size_t)srow * C2, ok);
        }
        const float* Wk = W2 + (size_t)kc * C2 * C2 + (size_t)(kt * 32) * C2 + n0;
        #pragma unroll
        for (int j = 0; j < 4; j++) {
            int k  = j * 8 + (tid >> 5);
            int n4 = (tid & 31) * 4;
            uint32_t d = (uint32_t)__cvta_generic_to_shared(b + k * 136 + n4);
            cpa16(d, Wk + (size_t)k * C2 + n4);
        }
        cp_commit();
    };

    float acc[4][4][4];
    #pragma unroll
    for (int mi = 0; mi < 4; mi++)
        #pragma unroll
        for (int ni = 0; ni < 4; ni++)
            #pragma unroll
            for (int j = 0; j < 4; j++) acc[mi][ni][j] = 0.f;

    auto comp = [&](int s) {
        const uint32_t* a = (const uint32_t*)(AsB + (s % 3) * ASZ);
        const uint32_t* b = (const uint32_t*)(BsB + (s % 3) * BSZ);
        #pragma unroll
        for (int ks = 0; ks < 4; ks++) {
            const int kb = ks * 8;
            uint32_t af[4][4];
            #pragma unroll
            for (int mi = 0; mi < 4; mi++) {
                int r0 = wm * 64 + mi * 16 + g;
                af[mi][0] = a[r0 * 36 + kb + t];
                af[mi][1] = a[(r0 + 8) * 36 + kb + t];
                af[mi][2] = a[r0 * 36 + kb + t + 4];
                af[mi][3] = a[(r0 + 8) * 36 + kb + t + 4];
            }
            uint32_t bf[4][2];
            #pragma unroll
            for (int ni = 0; ni < 4; ni++) {
                int c0 = wn * 32 + ni * 8 + g;
                bf[ni][0] = b[(kb + t) * 136 + c0];
                bf[ni][1] = b[(kb + t + 4) * 136 + c0];
            }
            #pragma unroll
            for (int mi = 0; mi < 4; mi++)
                #pragma unroll
                for (int ni = 0; ni < 4; ni++)
                    mma8(acc[mi][ni], af[mi], bf[ni]);
        }
    };

    stage(0);
    stage(1);
    #pragma unroll 1
    for (int s = 0; s < NIT; ++s) {
        cp_wait1();
        __syncthreads();
        if (s + 2 < NIT) stage(s + 2);
        comp(s);
    }

    #pragma unroll
    for (int mi = 0; mi < 4; mi++) {
        int r0 = m0 + wm * 64 + mi * 16 + g;
        #pragma unroll
        for (int ni = 0; ni < 4; ni++) {
            int c0 = n0 + wn * 32 + ni * 8 + t * 2;
            float2 v0, v1;
            v0.x = acc[mi][ni][0] + b2[c0];
            v0.y = acc[mi][ni][1] + b2[c0 + 1];
            v1.x = acc[mi][ni][2] + b2[c0];
            v1.y = acc[mi][ni][3] + b2[c0 + 1];
            *(float2*)(g_hc + (size_t)r0 * C2 + c0)       = v0;
            *(float2*)(g_hc + (size_t)(r0 + 8) * C2 + c0) = v1;
        }
    }
}

// ---------------- 4) GLU + BatchNorm (stores tf32-rounded) -------------------
__global__ void glu_bn(const float* __restrict__ bg, const float* __restrict__ bb_,
                       const float* __restrict__ bm, const float* __restrict__ bv) {
    int p = blockIdx.x * blockDim.x + threadIdx.x;   // float4 index
    int m = p >> 7;                                  // 128 float4 per row
    int c4 = (p & 127) * 4;
    float4 a  = *(const float4*)(g_hc + (size_t)m * C2 + c4);
    float4 gg = *(const float4*)(g_hc + (size_t)m * C2 + CC + c4);
    float4 o;
    {
        float s = bg[c4] * rsqrtf(bv[c4] + 1e-5f);
        o.x = tf32r((a.x * fsigmoid(gg.x) - bm[c4]) * s + bb_[c4]);
    }
    {
        float s = bg[c4 + 1] * rsqrtf(bv[c4 + 1] + 1e-5f);
        o.y = tf32r((a.y * fsigmoid(gg.y) - bm[c4 + 1]) * s + bb_[c4 + 1]);
    }
    {
        float s = bg[c4 + 2] * rsqrtf(bv[c4 + 2] + 1e-5f);
        o.z = tf32r((a.z * fsigmoid(gg.z) - bm[c4 + 2]) * s + bb_[c4 + 2]);
    }
    {
        float s = bg[c4 + 3] * rsqrtf(bv[c4 + 3] + 1e-5f);
        o.w = tf32r((a.w * fsigmoid(gg.w) - bm[c4 + 3]) * s + bb_[c4 + 3]);
    }
    *(float4*)(g_h2 + (size_t)m * CC + c4) = o;
}

// ---------------- launch -----------------------------------------------------
extern "C" void kernel_launch(void* const* d_in, const int* in_sizes, int n_in,
                              void* d_out, int out_size) {
    const float* x     = (const float*)d_in[0];
    const float* ln_g  = (const float*)d_in[1];
    const float* ln_b  = (const float*)d_in[2];
    const float* w1    = (const float*)d_in[3];
    const float* b1    = (const float*)d_in[4];
    const float* w2    = (const float*)d_in[5];
    const float* b2    = (const float*)d_in[6];
    const float* bn_g  = (const float*)d_in[7];
    const float* bn_b  = (const float*)d_in[8];
    const float* bn_m  = (const float*)d_in[9];
    const float* bn_v  = (const float*)d_in[10];
    const float* w3    = (const float*)d_in[11];
    const float* b3    = (const float*)d_in[12];
    float* out = (float*)d_out;

    const int smem_gemm = 3 * (128 * 36 + 128 * 36) * 4;   // 110592
    const int smem_conv = 3 * (128 * 36 + 32 * 136) * 4;   // 107520
    cudaFuncSetAttribute(gemm_wt<1, C2, 0, CC>,
                         cudaFuncAttributeMaxDynamicSharedMemorySize, smem_gemm);
    cudaFuncSetAttribute(gemm_wt<0, CC, 1, CC>,
                         cudaFuncAttributeMaxDynamicSharedMemorySize, smem_gemm);
    cudaFuncSetAttribute(conv_gemm,
                         cudaFuncAttributeMaxDynamicSharedMemorySize, smem_conv);

    // Resolve device-global weight buffers (host side, no allocation)
    float *w1r, *w2r, *w3r;
    cudaGetSymbolAddress((void**)&w1r, g_w1r);
    cudaGetSymbolAddress((void**)&w2r, g_w2r);
    cudaGetSymbolAddress((void**)&w3r, g_w3r);

    round_copy<<<(C2 * CC / 4 + 255) / 256, 256>>>(w1, w1r, C2 * CC / 4);
    round_copy<<<(5 * C2 * C2 / 4 + 255) / 256, 256>>>(w2, w2r, 5 * C2 * C2 / 4);
    round_copy<<<(CC * CC / 4 + 255) / 256, 256>>>(w3, w3r, CC * CC / 4);

    ln_kernel<<<MTOT, 256>>>(x, ln_g, ln_b);
    gemm_wt<1, C2, 0, CC><<<dim3(MTOT / 128, C2 / 128), 256, smem_gemm>>>(w1r, b1, nullptr);
    conv_gemm<<<dim3(MTOT / 128, C2 / 128), 256, smem_conv>>>(w2r, b2);
    glu_bn<<<(MTOT * CC / 4) / 256, 256>>>(bn_g, bn_b, bn_m, bn_v);
    gemm_wt<0, CC, 1, CC><<<dim3(MTOT / 128, CC / 128), 256, smem_gemm>>>(w3r, b3, out);
}

// round 9
// speedup vs baseline: 2.0174x; 1.3156x over previous
#include <cuda_runtime.h>
#include <cuda_fp16.h>
#include <cstdint>

// Problem constants
#define BQ   16
#define TT   1024
#define CC   512
#define MTOT (BQ * TT)      // 16384 rows (b,t)
#define C2   (2 * CC)       // 1024

// ---------------- scratch (device globals; no allocation allowed) -----------
__device__ float  g_xn[(size_t)MTOT * CC];      // LN output (tf32-rounded)
__device__ __half g_h1h[(size_t)MTOT * C2];     // GEMM1+SiLU output (fp16)
__device__ float  g_h2[(size_t)MTOT * CC];      // conv+GLU+BN output (tf32-rounded)
__device__ float  g_w1r[(size_t)C2 * CC];       // tf32-rounded weights
__device__ float  g_w3r[(size_t)CC * CC];
__device__ __half g_w2h[(size_t)5 * C2 * C2];   // w2 permuted+transposed [kc][p][i], fp16
__device__ float  g_b2p[C2];                    // permuted conv bias

// ---------------- helpers ---------------------------------------------------
__device__ __forceinline__ float tf32r(float x) {
    uint32_t u;
    asm("cvt.rna.tf32.f32 %0, %1;" : "=r"(u) : "f"(x));
    return __uint_as_float(u);
}

__device__ __forceinline__ void mma8(float (&d)[4], const uint32_t (&a)[4], const uint32_t (&b)[2]) {
    asm volatile(
        "mma.sync.aligned.m16n8k8.row.col.f32.tf32.tf32.f32 "
        "{%0,%1,%2,%3}, {%4,%5,%6,%7}, {%8,%9}, {%0,%1,%2,%3};\n"
        : "+f"(d[0]), "+f"(d[1]), "+f"(d[2]), "+f"(d[3])
        : "r"(a[0]), "r"(a[1]), "r"(a[2]), "r"(a[3]),
          "r"(b[0]), "r"(b[1]));
}
__device__ __forceinline__ void mma16h(float (&d)[4], const uint32_t (&a)[4], const uint32_t (&b)[2]) {
    asm volatile(
        "mma.sync.aligned.m16n8k16.row.col.f32.f16.f16.f32 "
        "{%0,%1,%2,%3}, {%4,%5,%6,%7}, {%8,%9}, {%0,%1,%2,%3};\n"
        : "+f"(d[0]), "+f"(d[1]), "+f"(d[2]), "+f"(d[3])
        : "r"(a[0]), "r"(a[1]), "r"(a[2]), "r"(a[3]),
          "r"(b[0]), "r"(b[1]));
}

__device__ __forceinline__ void cpa16(uint32_t dst, const void* src) {
    asm volatile("cp.async.cg.shared.global [%0], [%1], 16;\n" :: "r"(dst), "l"(src));
}
__device__ __forceinline__ void cpa16p(uint32_t dst, const void* src, bool pred) {
    int sz = pred ? 16 : 0;
    asm volatile("cp.async.cg.shared.global [%0], [%1], 16, %2;\n" :: "r"(dst), "l"(src), "r"(sz));
}
__device__ __forceinline__ void cp_commit() { asm volatile("cp.async.commit_group;\n"); }
__device__ __forceinline__ void cp_wait1() { asm volatile("cp.async.wait_group 1;\n"); }

__device__ __forceinline__ float fsigmoid(float v) { return 1.f / (1.f + __expf(-v)); }

// ---------------- 0) weight prep ---------------------------------------------
__global__ void round_copy(const float* __restrict__ src, float* __restrict__ dst, int n4) {
    int i = blockIdx.x * blockDim.x + threadIdx.x;
    if (i < n4) {
        float4 v = ((const float4*)src)[i];
        ((float4*)dst)[i] = make_float4(tf32r(v.x), tf32r(v.y), tf32r(v.z), tf32r(v.w));
    }
}

// w2[kc][i][o] -> g_w2h[kc][p][i] (fp16), p = (o<512) ? 2o : 2(o-512)+1
__global__ void w2_perm_half(const float* __restrict__ w2) {
    __shared__ float tile[32][33];
    int kc = blockIdx.z;
    int i0 = blockIdx.x * 32;
    int o0 = blockIdx.y * 32;
    int tx = threadIdx.x, ty = threadIdx.y;   // 32 x 8
    #pragma unroll
    for (int r = 0; r < 32; r += 8)
        tile[ty + r][tx] = w2[((size_t)kc * C2 + (i0 + ty + r)) * C2 + o0 + tx];
    __syncthreads();
    #pragma unroll
    for (int r = 0; r < 32; r += 8) {
        int o = o0 + ty + r;
        int p = (o < CC) ? (2 * o) : (2 * (o - CC) + 1);
        g_w2h[((size_t)kc * C2 + p) * C2 + i0 + tx] = __float2half_rn(tile[tx][ty + r]);
    }
}

__global__ void b2_perm(const float* __restrict__ b2) {
    int p = blockIdx.x * blockDim.x + threadIdx.x;
    if (p < C2) {
        int ch = (p & 1) ? (CC + (p >> 1)) : (p >> 1);
        g_b2p[p] = b2[ch];
    }
}

// ---------------- 1) LayerNorm (stores tf32-rounded) -------------------------
__global__ void ln_kernel(const float* __restrict__ x,
                          const float* __restrict__ lg,
                          const float* __restrict__ lb) {
    int row = blockIdx.x;
    const float2* xin = (const float2*)(x + (size_t)row * CC);
    float2 v = xin[threadIdx.x];
    float s = v.x + v.y;
    float q = v.x * v.x + v.y * v.y;
    #pragma unroll
    for (int o = 16; o; o >>= 1) {
        s += __shfl_xor_sync(0xffffffffu, s, o);
        q += __shfl_xor_sync(0xffffffffu, q, o);
    }
    __shared__ float ss[8], sq[8];
    __shared__ float mu_s, rs_s;
    int w = threadIdx.x >> 5, l = threadIdx.x & 31;
    if (l == 0) { ss[w] = s; sq[w] = q; }
    __syncthreads();
    if (threadIdx.x == 0) {
        float S = 0.f, Q = 0.f;
        #pragma unroll
        for (int i = 0; i < 8; i++) { S += ss[i]; Q += sq[i]; }
        float mu = S * (1.f / CC);
        float var = Q * (1.f / CC) - mu * mu;
        mu_s = mu;
        rs_s = rsqrtf(var + 1e-5f);
    }
    __syncthreads();
    float mu = mu_s, rs = rs_s;
    int c = threadIdx.x * 2;
    float2 o;
    o.x = tf32r((v.x - mu) * rs * lg[c]     + lb[c]);
    o.y = tf32r((v.y - mu) * rs * lg[c + 1] + lb[c + 1]);
    ((float2*)(g_xn + (size_t)row * CC))[threadIdx.x] = o;
}

// ---------------- 2/5) tf32 GEMM (proven R6 path) ----------------------------
// MODE 0: A = g_xn -> g_h1h (silu, fp16 store). MODE 1: A = g_h2 -> out (float).
template <int ACT, int N, int MODE, int KD>
__global__ __launch_bounds__(256, 2)
void gemm_wt(const float* __restrict__ W, const float* __restrict__ bias,
             float* __restrict__ outParam) {
    extern __shared__ float sm[];
    constexpr int ASZ = 128 * 36;
    constexpr int BSZ = 128 * 36;
    float* AsB = sm;
    float* BsB = sm + 3 * ASZ;
    constexpr int KT = KD / 32;

    const float* A = (MODE == 0) ? g_xn : g_h2;

    const int m0 = blockIdx.x * 128, n0 = blockIdx.y * 128;
    const int tid = threadIdx.x;
    const int lane = tid & 31, warp = tid >> 5;
    const int wm = warp & 1, wn = warp >> 1;
    const int g = lane >> 2, t = lane & 3;
    const int ar = tid >> 3, ac = (tid & 7) * 4;

    auto stage = [&](int s) {
        float* a = AsB + (s % 3) * ASZ;
        float* b = BsB + (s % 3) * BSZ;
        const float* Ap = A + (size_t)(m0 + ar) * KD + s * 32 + ac;
        #pragma unroll
        for (int i = 0; i < 4; i++) {
            uint32_t d = (uint32_t)__cvta_generic_to_shared(a + (ar + i * 32) * 36 + ac);
            cpa16(d, Ap + (size_t)(i * 32) * KD);
        }
        #pragma unroll
        for (int j = 0; j < 4; j++) {
            int n  = j * 32 + (tid >> 3);
            int kc = (tid & 7) * 4;
            uint32_t d = (uint32_t)__cvta_generic_to_shared(b + n * 36 + kc);
            cpa16(d, W + (size_t)(n0 + n) * KD + s * 32 + kc);
        }
        cp_commit();
    };

    float acc[4][4][4];
    #pragma unroll
    for (int mi = 0; mi < 4; mi++)
        #pragma unroll
        for (int ni = 0; ni < 4; ni++)
            #pragma unroll
            for (int j = 0; j < 4; j++) acc[mi][ni][j] = 0.f;

    auto comp = [&](int s) {
        const uint32_t* a = (const uint32_t*)(AsB + (s % 3) * ASZ);
        const uint32_t* b = (const uint32_t*)(BsB + (s % 3) * BSZ);
        #pragma unroll
        for (int ks = 0; ks < 4; ks++) {
            const int kb = ks * 8;
            uint32_t af[4][4];
            #pragma unroll
            for (int mi = 0; mi < 4; mi++) {
                int r0 = wm * 64 + mi * 16 + g;
                af[mi][0] = a[r0 * 36 + kb + t];
                af[mi][1] = a[(r0 + 8) * 36 + kb + t];
                af[mi][2] = a[r0 * 36 + kb + t + 4];
                af[mi][3] = a[(r0 + 8) * 36 + kb + t + 4];
            }
            uint32_t bf[4][2];
            #pragma unroll
            for (int ni = 0; ni < 4; ni++) {
                int c0 = wn * 32 + ni * 8 + g;
                bf[ni][0] = b[c0 * 36 + kb + t];
                bf[ni][1] = b[c0 * 36 + kb + t + 4];
            }
            #pragma unroll
            for (int mi = 0; mi < 4; mi++)
                #pragma unroll
                for (int ni = 0; ni < 4; ni++)
                    mma8(acc[mi][ni], af[mi], bf[ni]);
        }
    };

    stage(0);
    stage(1);
    #pragma unroll 1
    for (int kt = 0; kt < KT; ++kt) {
        cp_wait1();
        __syncthreads();
        if (kt + 2 < KT) stage(kt + 2);
        comp(kt);
    }

    #pragma unroll
    for (int mi = 0; mi < 4; mi++) {
        int r0 = m0 + wm * 64 + mi * 16 + g;
        #pragma unroll
        for (int ni = 0; ni < 4; ni++) {
            int c0 = n0 + wn * 32 + ni * 8 + t * 2;
            float2 v0, v1;
            v0.x = acc[mi][ni][0] + bias[c0];
            v0.y = acc[mi][ni][1] + bias[c0 + 1];
            v1.x = acc[mi][ni][2] + bias[c0];
            v1.y = acc[mi][ni][3] + bias[c0 + 1];
            if (MODE == 0) {
                // SiLU, then fp16 store for the conv stage
                v0.x = v0.x * fsigmoid(v0.x); v0.y = v0.y * fsigmoid(v0.y);
                v1.x = v1.x * fsigmoid(v1.x); v1.y = v1.y * fsigmoid(v1.y);
                *(__half2*)(g_h1h + (size_t)r0 * N + c0)       = __floats2half2_rn(v0.x, v0.y);
                *(__half2*)(g_h1h + (size_t)(r0 + 8) * N + c0) = __floats2half2_rn(v1.x, v1.y);
            } else {
                *(float2*)(outParam + (size_t)r0 * N + c0)       = v0;
                *(float2*)(outParam + (size_t)(r0 + 8) * N + c0) = v1;
            }
        }
    }
}

// ---------------- 3) Conv1d (K=5) fp16 GEMM + fused GLU+BN -------------------
// Permuted N: col p=2j is a-channel j, p=2j+1 is g-channel j. Each thread's
// accumulator pair (c0, c0+1) = (a_j, g_j) -> GLU+BN in registers -> g_h2[.,j].
__global__ __launch_bounds__(256, 2)
void conv_fp16(const float* __restrict__ bg, const float* __restrict__ bb_,
               const float* __restrict__ bm, const float* __restrict__ bv) {
    extern __shared__ float smf[];
    __half* smh = (__half*)smf;
    constexpr int ROWW = 40;          // halves per row (80 B, 20-word stride: bank-bijective)
    constexpr int TSZ  = 128 * ROWW;  // halves per tile
    __half* AsB = smh;                // 3 stages A
    __half* BsB = smh + 3 * TSZ;      // 3 stages B
    constexpr int NIT = 160;          // 32 K-tiles x 5 taps

    const int m0 = blockIdx.x * 128, n0 = blockIdx.y * 128;
    const int bb = m0 >> 10, t0 = m0 & 1023;
    const int tid = threadIdx.x;
    const int lane = tid & 31, warp = tid >> 5;
    const int wm = warp & 1, wn = warp >> 1;
    const int g = lane >> 2, t = lane & 3;

    auto stage = [&](int s) {
        int kt = s / 5;
        int kc = s - kt * 5;
        int shift = kc - 2;
        __half* a = AsB + (s % 3) * TSZ;
        __half* b = BsB + (s % 3) * TSZ;
        const __half* Ab = g_h1h + (size_t)(bb * TT) * C2 + kt * 32;
        const __half* Bb = g_w2h + ((size_t)kc * C2 + n0) * C2 + kt * 32;
        #pragma unroll
        for (int p = 0; p < 2; p++) {
            int c = tid * 2 + p;          // 512 chunks of 16B
            int row = c >> 2, kh = c & 3;
            uint32_t dA = (uint32_t)__cvta_generic_to_shared(a + row * ROWW + kh * 8);
            uint32_t dB = (uint32_t)__cvta_generic_to_shared(b + row * ROWW + kh * 8);
            int trow = t0 + row + shift;
            bool ok = (trow >= 0) && (trow < TT);
            cpa16p(dA, Ab + (size_t)(ok ? trow : 0) * C2 + kh * 8, ok);
            cpa16(dB, Bb + (size_t)row * C2 + kh * 8);
        }
        cp_commit();
    };

    float acc[4][4][4];
    #pragma unroll
    for (int mi = 0; mi < 4; mi++)
        #pragma unroll
        for (int ni = 0; ni < 4; ni++)
            #pragma unroll
            for (int j = 0; j < 4; j++) acc[mi][ni][j] = 0.f;

    auto comp = [&](int s) {
        const uint32_t* a = (const uint32_t*)(AsB + (s % 3) * TSZ);
        const uint32_t* b = (const uint32_t*)(BsB + (s % 3) * TSZ);
        #pragma unroll
        for (int ks = 0; ks < 2; ks++) {       // 2 x k16 = K32
            const int kb = ks * 8;             // 32-bit word offset
            uint32_t af[4][4];
            #pragma unroll
            for (int mi = 0; mi < 4; mi++) {
                int r0 = wm * 64 + mi * 16 + g;
                af[mi][0] = a[r0 * 20 + kb + t];
                af[mi][1] = a[(r0 + 8) * 20 + kb + t];
                af[mi][2] = a[r0 * 20 + kb + t + 4];
                af[mi][3] = a[(r0 + 8) * 20 + kb + t + 4];
            }
            uint32_t bf[4][2];
            #pragma unroll
            for (int ni = 0; ni < 4; ni++) {
                int c0 = wn * 32 + ni * 8 + g;
                bf[ni][0] = b[c0 * 20 + kb + t];
                bf[ni][1] = b[c0 * 20 + kb + t + 4];
            }
            #pragma unroll
            for (int mi = 0; mi < 4; mi++)
                #pragma unroll
                for (int ni = 0; ni < 4; ni++)
                    mma16h(acc[mi][ni], af[mi], bf[ni]);
        }
    };

    stage(0);
    stage(1);
    #pragma unroll 1
    for (int s = 0; s < NIT; ++s) {
        cp_wait1();
        __syncthreads();
        if (s + 2 < NIT) stage(s + 2);
        comp(s);
    }

    // Fused epilogue: bias -> GLU -> BN -> tf32 round -> g_h2
    #pragma unroll
    for (int mi = 0; mi < 4; mi++) {
        int r0 = m0 + wm * 64 + mi * 16 + g;
        #pragma unroll
        for (int ni = 0; ni < 4; ni++) {
            int c0 = n0 + wn * 32 + ni * 8 + t * 2;
            int j  = c0 >> 1;
            float ba = g_b2p[c0], bgg = g_b2p[c0 + 1];
            float sc = bg[j] * rsqrtf(bv[j] + 1e-5f);
            float mean = bm[j], beta = bb_[j];
            float a0 = acc[mi][ni][0] + ba, g0 = acc[mi][ni][1] + bgg;
            float a1 = acc[mi][ni][2] + ba, g1 = acc[mi][ni][3] + bgg;
            float o0 = a0 * fsigmoid(g0);
            float o1 = a1 * fsigmoid(g1);
            g_h2[(size_t)r0 * CC + j]       = tf32r((o0 - mean) * sc + beta);
            g_h2[(size_t)(r0 + 8) * CC + j] = tf32r((o1 - mean) * sc + beta);
        }
    }
}

// ---------------- launch -----------------------------------------------------
extern "C" void kernel_launch(void* const* d_in, const int* in_sizes, int n_in,
                              void* d_out, int out_size) {
    const float* x     = (const float*)d_in[0];
    const float* ln_g  = (const float*)d_in[1];
    const float* ln_b  = (const float*)d_in[2];
    const float* w1    = (const float*)d_in[3];
    const float* b1    = (const float*)d_in[4];
    const float* w2    = (const float*)d_in[5];
    const float* b2    = (const float*)d_in[6];
    const float* bn_g  = (const float*)d_in[7];
    const float* bn_b  = (const float*)d_in[8];
    const float* bn_m  = (const float*)d_in[9];
    const float* bn_v  = (const float*)d_in[10];
    const float* w3    = (const float*)d_in[11];
    const float* b3    = (const float*)d_in[12];
    float* out = (float*)d_out;

    const int smem_gemm = 3 * (128 * 36 + 128 * 36) * 4;   // 110592
    const int smem_conv = 6 * 128 * 40 * 2;                // 61440
    cudaFuncSetAttribute(gemm_wt<1, C2, 0, CC>,
                         cudaFuncAttributeMaxDynamicSharedMemorySize, smem_gemm);
    cudaFuncSetAttribute(gemm_wt<0, CC, 1, CC>,
                         cudaFuncAttributeMaxDynamicSharedMemorySize, smem_gemm);
    cudaFuncSetAttribute(conv_fp16,
                         cudaFuncAttributeMaxDynamicSharedMemorySize, smem_conv);

    float *w1r, *w3r;
    cudaGetSymbolAddress((void**)&w1r, g_w1r);
    cudaGetSymbolAddress((void**)&w3r, g_w3r);

    round_copy<<<(C2 * CC / 4 + 255) / 256, 256>>>(w1, w1r, C2 * CC / 4);
    round_copy<<<(CC * CC / 4 + 255) / 256, 256>>>(w3, w3r, CC * CC / 4);
    w2_perm_half<<<dim3(C2 / 32, C2 / 32, 5), dim3(32, 8)>>>(w2);
    b2_perm<<<4, 256>>>(b2);

    ln_kernel<<<MTOT, 256>>>(x, ln_g, ln_b);
    gemm_wt<1, C2, 0, CC><<<dim3(MTOT / 128, C2 / 128), 256, smem_gemm>>>(w1r, b1, nullptr);
    conv_fp16<<<dim3(MTOT / 128, C2 / 128), 256, smem_conv>>>(bn_g, bn_b, bn_m, bn_v);
    gemm_wt<0, CC, 1, CC><<<dim3(MTOT / 128, CC / 128), 256, smem_gemm>>>(w3r, b3, out);
}

// round 10
// speedup vs baseline: 2.1156x; 1.0487x over previous
#include <cuda_runtime.h>
#include <cuda_fp16.h>
#include <cstdint>

// Problem constants
#define BQ   16
#define TT   1024
#define CC   512
#define MTOT (BQ * TT)      // 16384 rows (b,t)
#define C2   (2 * CC)       // 1024

// ---------------- scratch (device globals; no allocation allowed) -----------
__device__ __half g_xnh[(size_t)MTOT * CC];     // LN output (fp16)
__device__ __half g_h1h[(size_t)MTOT * C2];     // GEMM1+SiLU output (fp16)
__device__ __half g_h2h[(size_t)MTOT * CC];     // conv+GLU+BN output (fp16)
__device__ __half g_w1h[(size_t)C2 * CC];       // fp16 weights
__device__ __half g_w3h[(size_t)CC * CC];
__device__ __half g_w2h[(size_t)5 * C2 * C2];   // w2 permuted+transposed [kc][p][i], fp16
__device__ float  g_b2p[C2];                    // permuted conv bias

// ---------------- helpers ---------------------------------------------------
__device__ __forceinline__ void mma16h(float (&d)[4], const uint32_t (&a)[4], const uint32_t (&b)[2]) {
    asm volatile(
        "mma.sync.aligned.m16n8k16.row.col.f32.f16.f16.f32 "
        "{%0,%1,%2,%3}, {%4,%5,%6,%7}, {%8,%9}, {%0,%1,%2,%3};\n"
        : "+f"(d[0]), "+f"(d[1]), "+f"(d[2]), "+f"(d[3])
        : "r"(a[0]), "r"(a[1]), "r"(a[2]), "r"(a[3]),
          "r"(b[0]), "r"(b[1]));
}

__device__ __forceinline__ void cpa16(uint32_t dst, const void* src) {
    asm volatile("cp.async.cg.shared.global [%0], [%1], 16;\n" :: "r"(dst), "l"(src));
}
__device__ __forceinline__ void cpa16p(uint32_t dst, const void* src, bool pred) {
    int sz = pred ? 16 : 0;
    asm volatile("cp.async.cg.shared.global [%0], [%1], 16, %2;\n" :: "r"(dst), "l"(src), "r"(sz));
}
__device__ __forceinline__ void cp_commit() { asm volatile("cp.async.commit_group;\n"); }
__device__ __forceinline__ void cp_wait1() { asm volatile("cp.async.wait_group 1;\n"); }

__device__ __forceinline__ float fsigmoid(float v) { return 1.f / (1.f + __expf(-v)); }

// ---------------- 0) weight prep ---------------------------------------------
__global__ void half_copy(const float* __restrict__ src, __half* __restrict__ dst, int n4) {
    int i = blockIdx.x * blockDim.x + threadIdx.x;
    if (i < n4) {
        float4 v = ((const float4*)src)[i];
        __half2 h0 = __floats2half2_rn(v.x, v.y);
        __half2 h1 = __floats2half2_rn(v.z, v.w);
        ((__half2*)dst)[i * 2]     = h0;
        ((__half2*)dst)[i * 2 + 1] = h1;
    }
}

// w2[kc][i][o] -> g_w2h[kc][p][i] (fp16), p = (o<512) ? 2o : 2(o-512)+1
__global__ void w2_perm_half(const float* __restrict__ w2) {
    __shared__ float tile[32][33];
    int kc = blockIdx.z;
    int i0 = blockIdx.x * 32;
    int o0 = blockIdx.y * 32;
    int tx = threadIdx.x, ty = threadIdx.y;   // 32 x 8
    #pragma unroll
    for (int r = 0; r < 32; r += 8)
        tile[ty + r][tx] = w2[((size_t)kc * C2 + (i0 + ty + r)) * C2 + o0 + tx];
    __syncthreads();
    #pragma unroll
    for (int r = 0; r < 32; r += 8) {
        int o = o0 + ty + r;
        int p = (o < CC) ? (2 * o) : (2 * (o - CC) + 1);
        g_w2h[((size_t)kc * C2 + p) * C2 + i0 + tx] = __float2half_rn(tile[tx][ty + r]);
    }
}

__global__ void b2_perm(const float* __restrict__ b2) {
    int p = blockIdx.x * blockDim.x + threadIdx.x;
    if (p < C2) {
        int ch = (p & 1) ? (CC + (p >> 1)) : (p >> 1);
        g_b2p[p] = b2[ch];
    }
}

// ---------------- 1) LayerNorm (stores fp16) ---------------------------------
__global__ void ln_kernel(const float* __restrict__ x,
                          const float* __restrict__ lg,
                          const float* __restrict__ lb) {
    int row = blockIdx.x;
    const float2* xin = (const float2*)(x + (size_t)row * CC);
    float2 v = xin[threadIdx.x];
    float s = v.x + v.y;
    float q = v.x * v.x + v.y * v.y;
    #pragma unroll
    for (int o = 16; o; o >>= 1) {
        s += __shfl_xor_sync(0xffffffffu, s, o);
        q += __shfl_xor_sync(0xffffffffu, q, o);
    }
    __shared__ float ss[8], sq[8];
    __shared__ float mu_s, rs_s;
    int w = threadIdx.x >> 5, l = threadIdx.x & 31;
    if (l == 0) { ss[w] = s; sq[w] = q; }
    __syncthreads();
    if (threadIdx.x == 0) {
        float S = 0.f, Q = 0.f;
        #pragma unroll
        for (int i = 0; i < 8; i++) { S += ss[i]; Q += sq[i]; }
        float mu = S * (1.f / CC);
        float var = Q * (1.f / CC) - mu * mu;
        mu_s = mu;
        rs_s = rsqrtf(var + 1e-5f);
    }
    __syncthreads();
    float mu = mu_s, rs = rs_s;
    int c = threadIdx.x * 2;
    float ox = (v.x - mu) * rs * lg[c]     + lb[c];
    float oy = (v.y - mu) * rs * lg[c + 1] + lb[c + 1];
    ((__half2*)(g_xnh + (size_t)row * CC))[threadIdx.x] = __floats2half2_rn(ox, oy);
}

// ---------------- 2/5) fp16 GEMM:  C = act(A @ W^T + bias) -------------------
// Tile 128x128xK32, 8 warps (2x4), warp tile 64x32. 3-stage cp.async pipeline.
// A: M x KD fp16 row-major. W: N x KD fp16 row-major (k-contiguous).
// MODE 0: A = g_xnh -> g_h1h (SiLU, fp16 store). MODE 1: A = g_h2h -> out (fp32).
template <int N, int MODE, int KD>
__global__ __launch_bounds__(256, 2)
void gemm_h(const __half* __restrict__ W, const float* __restrict__ bias,
            float* __restrict__ outParam) {
    extern __shared__ float smf[];
    __half* smh = (__half*)smf;
    constexpr int ROWW = 40;          // halves per row (80 B; 20-word stride bank-bijective)
    constexpr int TSZ  = 128 * ROWW;
    __half* AsB = smh;
    __half* BsB = smh + 3 * TSZ;
    constexpr int KT = KD / 32;

    const __half* A = (MODE == 0) ? g_xnh : g_h2h;

    const int m0 = blockIdx.x * 128, n0 = blockIdx.y * 128;
    const int tid = threadIdx.x;
    const int lane = tid & 31, warp = tid >> 5;
    const int wm = warp & 1, wn = warp >> 1;
    const int g = lane >> 2, t = lane & 3;

    auto stage = [&](int s) {
        __half* a = AsB + (s % 3) * TSZ;
        __half* b = BsB + (s % 3) * TSZ;
        const __half* Ab = A + (size_t)m0 * KD + s * 32;
        const __half* Bb = W + (size_t)n0 * KD + s * 32;
        #pragma unroll
        for (int p = 0; p < 2; p++) {
            int c = tid * 2 + p;          // 512 chunks of 16B per operand
            int row = c >> 2, kh = c & 3;
            uint32_t dA = (uint32_t)__cvta_generic_to_shared(a + row * ROWW + kh * 8);
            uint32_t dB = (uint32_t)__cvta_generic_to_shared(b + row * ROWW + kh * 8);
            cpa16(dA, Ab + (size_t)row * KD + kh * 8);
            cpa16(dB, Bb + (size_t)row * KD + kh * 8);
        }
        cp_commit();
    };

    float acc[4][4][4];
    #pragma unroll
    for (int mi = 0; mi < 4; mi++)
        #pragma unroll
        for (int ni = 0; ni < 4; ni++)
            #pragma unroll
            for (int j = 0; j < 4; j++) acc[mi][ni][j] = 0.f;

    auto comp = [&](int s) {
        const uint32_t* a = (const uint32_t*)(AsB + (s % 3) * TSZ);
        const uint32_t* b = (const uint32_t*)(BsB + (s % 3) * TSZ);
        #pragma unroll
        for (int ks = 0; ks < 2; ks++) {       // 2 x k16 = K32
            const int kb = ks * 8;
            uint32_t af[4][4];
            #pragma unroll
            for (int mi = 0; mi < 4; mi++) {
                int r0 = wm * 64 + mi * 16 + g;
                af[mi][0] = a[r0 * 20 + kb + t];
                af[mi][1] = a[(r0 + 8) * 20 + kb + t];
                af[mi][2] = a[r0 * 20 + kb + t + 4];
                af[mi][3] = a[(r0 + 8) * 20 + kb + t + 4];
            }
            uint32_t bf[4][2];
            #pragma unroll
            for (int ni = 0; ni < 4; ni++) {
                int c0 = wn * 32 + ni * 8 + g;
                bf[ni][0] = b[c0 * 20 + kb + t];
                bf[ni][1] = b[c0 * 20 + kb + t + 4];
            }
            #pragma unroll
            for (int mi = 0; mi < 4; mi++)
                #pragma unroll
                for (int ni = 0; ni < 4; ni++)
                    mma16h(acc[mi][ni], af[mi], bf[ni]);
        }
    };

    stage(0);
    stage(1);
    #pragma unroll 1
    for (int kt = 0; kt < KT; ++kt) {
        cp_wait1();
        __syncthreads();
        if (kt + 2 < KT) stage(kt + 2);
        comp(kt);
    }

    #pragma unroll
    for (int mi = 0; mi < 4; mi++) {
        int r0 = m0 + wm * 64 + mi * 16 + g;
        #pragma unroll
        for (int ni = 0; ni < 4; ni++) {
            int c0 = n0 + wn * 32 + ni * 8 + t * 2;
            float2 v0, v1;
            v0.x = acc[mi][ni][0] + bias[c0];
            v0.y = acc[mi][ni][1] + bias[c0 + 1];
            v1.x = acc[mi][ni][2] + bias[c0];
            v1.y = acc[mi][ni][3] + bias[c0 + 1];
            if (MODE == 0) {
                v0.x = v0.x * fsigmoid(v0.x); v0.y = v0.y * fsigmoid(v0.y);
                v1.x = v1.x * fsigmoid(v1.x); v1.y = v1.y * fsigmoid(v1.y);
                *(__half2*)(g_h1h + (size_t)r0 * N + c0)       = __floats2half2_rn(v0.x, v0.y);
                *(__half2*)(g_h1h + (size_t)(r0 + 8) * N + c0) = __floats2half2_rn(v1.x, v1.y);
            } else {
                *(float2*)(outParam + (size_t)r0 * N + c0)       = v0;
                *(float2*)(outParam + (size_t)(r0 + 8) * N + c0) = v1;
            }
        }
    }
}

// ---------------- 3) Conv1d (K=5) fp16 GEMM + fused GLU+BN -------------------
// Permuted N: col p=2j is a-channel j, p=2j+1 is g-channel j. Each thread's
// accumulator pair (c0, c0+1) = (a_j, g_j) -> GLU+BN in registers -> g_h2h[.,j].
__global__ __launch_bounds__(256, 2)
void conv_fp16(const float* __restrict__ bg, const float* __restrict__ bb_,
               const float* __restrict__ bm, const float* __restrict__ bv) {
    extern __shared__ float smf[];
    __half* smh = (__half*)smf;
    constexpr int ROWW = 40;
    constexpr int TSZ  = 128 * ROWW;
    __half* AsB = smh;
    __half* BsB = smh + 3 * TSZ;
    constexpr int NIT = 160;          // 32 K-tiles x 5 taps

    const int m0 = blockIdx.x * 128, n0 = blockIdx.y * 128;
    const int bb = m0 >> 10, t0 = m0 & 1023;
    const int tid = threadIdx.x;
    const int lane = tid & 31, warp = tid >> 5;
    const int wm = warp & 1, wn = warp >> 1;
    const int g = lane >> 2, t = lane & 3;

    auto stage = [&](int s) {
        int kt = s / 5;
        int kc = s - kt * 5;
        int shift = kc - 2;
        __half* a = AsB + (s % 3) * TSZ;
        __half* b = BsB + (s % 3) * TSZ;
        const __half* Ab = g_h1h + (size_t)(bb * TT) * C2 + kt * 32;
        const __half* Bb = g_w2h + ((size_t)kc * C2 + n0) * C2 + kt * 32;
        #pragma unroll
        for (int p = 0; p < 2; p++) {
            int c = tid * 2 + p;
            int row = c >> 2, kh = c & 3;
            uint32_t dA = (uint32_t)__cvta_generic_to_shared(a + row * ROWW + kh * 8);
            uint32_t dB = (uint32_t)__cvta_generic_to_shared(b + row * ROWW + kh * 8);
            int trow = t0 + row + shift;
            bool ok = (trow >= 0) && (trow < TT);
            cpa16p(dA, Ab + (size_t)(ok ? trow : 0) * C2 + kh * 8, ok);
            cpa16(dB, Bb + (size_t)row * C2 + kh * 8);
        }
        cp_commit();
    };

    float acc[4][4][4];
    #pragma unroll
    for (int mi = 0; mi < 4; mi++)
        #pragma unroll
        for (int ni = 0; ni < 4; ni++)
            #pragma unroll
            for (int j = 0; j < 4; j++) acc[mi][ni][j] = 0.f;

    auto comp = [&](int s) {
        const uint32_t* a = (const uint32_t*)(AsB + (s % 3) * TSZ);
        const uint32_t* b = (const uint32_t*)(BsB + (s % 3) * TSZ);
        #pragma unroll
        for (int ks = 0; ks < 2; ks++) {
            const int kb = ks * 8;
            uint32_t af[4][4];
            #pragma unroll
            for (int mi = 0; mi < 4; mi++) {
                int r0 = wm * 64 + mi * 16 + g;
                af[mi][0] = a[r0 * 20 + kb + t];
                af[mi][1] = a[(r0 + 8) * 20 + kb + t];
                af[mi][2] = a[r0 * 20 + kb + t + 4];
                af[mi][3] = a[(r0 + 8) * 20 + kb + t + 4];
            }
            uint32_t bf[4][2];
            #pragma unroll
            for (int ni = 0; ni < 4; ni++) {
                int c0 = wn * 32 + ni * 8 + g;
                bf[ni][0] = b[c0 * 20 + kb + t];
                bf[ni][1] = b[c0 * 20 + kb + t + 4];
            }
            #pragma unroll
            for (int mi = 0; mi < 4; mi++)
                #pragma unroll
                for (int ni = 0; ni < 4; ni++)
                    mma16h(acc[mi][ni], af[mi], bf[ni]);
        }
    };

    stage(0);
    stage(1);
    #pragma unroll 1
    for (int s = 0; s < NIT; ++s) {
        cp_wait1();
        __syncthreads();
        if (s + 2 < NIT) stage(s + 2);
        comp(s);
    }

    // Fused epilogue: bias -> GLU -> BN -> fp16 -> g_h2h
    #pragma unroll
    for (int mi = 0; mi < 4; mi++) {
        int r0 = m0 + wm * 64 + mi * 16 + g;
        #pragma unroll
        for (int ni = 0; ni < 4; ni++) {
            int c0 = n0 + wn * 32 + ni * 8 + t * 2;
            int j  = c0 >> 1;
            float ba = g_b2p[c0], bgg = g_b2p[c0 + 1];
            float sc = bg[j] * rsqrtf(bv[j] + 1e-5f);
            float mean = bm[j], beta = bb_[j];
            float a0 = acc[mi][ni][0] + ba, g0 = acc[mi][ni][1] + bgg;
            float a1 = acc[mi][ni][2] + ba, g1 = acc[mi][ni][3] + bgg;
            float o0 = a0 * fsigmoid(g0);
            float o1 = a1 * fsigmoid(g1);
            g_h2h[(size_t)r0 * CC + j]       = __float2half_rn((o0 - mean) * sc + beta);
            g_h2h[(size_t)(r0 + 8) * CC + j] = __float2half_rn((o1 - mean) * sc + beta);
        }
    }
}

// ---------------- launch -----------------------------------------------------
extern "C" void kernel_launch(void* const* d_in, const int* in_sizes, int n_in,
                              void* d_out, int out_size) {
    const float* x     = (const float*)d_in[0];
    const float* ln_g  = (const float*)d_in[1];
    const float* ln_b  = (const float*)d_in[2];
    const float* w1    = (const float*)d_in[3];
    const float* b1    = (const float*)d_in[4];
    const float* w2    = (const float*)d_in[5];
    const float* b2    = (const float*)d_in[6];
    const float* bn_g  = (const float*)d_in[7];
    const float* bn_b  = (const float*)d_in[8];
    const float* bn_m  = (const float*)d_in[9];
    const float* bn_v  = (const float*)d_in[10];
    const float* w3    = (const float*)d_in[11];
    const float* b3    = (const float*)d_in[12];
    float* out = (float*)d_out;

    const int smem_half = 6 * 128 * 40 * 2;                // 61440
    cudaFuncSetAttribute(gemm_h<C2, 0, CC>,
                         cudaFuncAttributeMaxDynamicSharedMemorySize, smem_half);
    cudaFuncSetAttribute(gemm_h<CC, 1, CC>,
                         cudaFuncAttributeMaxDynamicSharedMemorySize, smem_half);
    cudaFuncSetAttribute(conv_fp16,
                         cudaFuncAttributeMaxDynamicSharedMemorySize, smem_half);

    __half *w1h, *w3h;
    cudaGetSymbolAddress((void**)&w1h, g_w1h);
    cudaGetSymbolAddress((void**)&w3h, g_w3h);

    half_copy<<<(C2 * CC / 4 + 255) / 256, 256>>>(w1, w1h, C2 * CC / 4);
    half_copy<<<(CC * CC / 4 + 255) / 256, 256>>>(w3, w3h, CC * CC / 4);
    w2_perm_half<<<dim3(C2 / 32, C2 / 32, 5), dim3(32, 8)>>>(w2);
    b2_perm<<<4, 256>>>(b2);

    ln_kernel<<<MTOT, 256>>>(x, ln_g, ln_b);
    gemm_h<C2, 0, CC><<<dim3(MTOT / 128, C2 / 128), 256, smem_half>>>(w1h, b1, nullptr);
    conv_fp16<<<dim3(MTOT / 128, C2 / 128), 256, smem_half>>>(bn_g, bn_b, bn_m, bn_v);
    gemm_h<CC, 1, CC><<<dim3(MTOT / 128, CC / 128), 256, smem_half>>>(w3h, b3, out);
}

// round 11
// speedup vs baseline: 2.6860x; 1.2696x over previous
#include <cuda_runtime.h>
#include <cuda_fp16.h>
#include <cstdint>

// Problem constants
#define BQ   16
#define TT   1024
#define CC   512
#define MTOT (BQ * TT)      // 16384 rows (b,t)
#define C2   (2 * CC)       // 1024

// ---------------- scratch (device globals; no allocation allowed) -----------
__device__ __half g_xnh[(size_t)MTOT * CC];     // LN output (fp16)
__device__ __half g_h1h[(size_t)MTOT * C2];     // GEMM1+SiLU output (fp16)
__device__ __half g_h2h[(size_t)MTOT * CC];     // conv+GLU+BN output (fp16)
__device__ __half g_w1h[(size_t)C2 * CC];       // fp16 weights
__device__ __half g_w3h[(size_t)CC * CC];
__device__ __half g_w2h[(size_t)5 * C2 * C2];   // w2 permuted+transposed [kc][p][i], fp16
__device__ float  g_b2p[C2];                    // permuted conv bias

// ---------------- helpers ---------------------------------------------------
__device__ __forceinline__ void mma16h(float (&d)[4], const uint32_t (&a)[4], const uint32_t (&b)[2]) {
    asm volatile(
        "mma.sync.aligned.m16n8k16.row.col.f32.f16.f16.f32 "
        "{%0,%1,%2,%3}, {%4,%5,%6,%7}, {%8,%9}, {%0,%1,%2,%3};\n"
        : "+f"(d[0]), "+f"(d[1]), "+f"(d[2]), "+f"(d[3])
        : "r"(a[0]), "r"(a[1]), "r"(a[2]), "r"(a[3]),
          "r"(b[0]), "r"(b[1]));
}

__device__ __forceinline__ void cpa16(uint32_t dst, const void* src) {
    asm volatile("cp.async.cg.shared.global [%0], [%1], 16;\n" :: "r"(dst), "l"(src));
}
__device__ __forceinline__ void cpa16p(uint32_t dst, const void* src, bool pred) {
    int sz = pred ? 16 : 0;
    asm volatile("cp.async.cg.shared.global [%0], [%1], 16, %2;\n" :: "r"(dst), "l"(src), "r"(sz));
}
__device__ __forceinline__ void cp_commit() { asm volatile("cp.async.commit_group;\n"); }
__device__ __forceinline__ void cp_wait1() { asm volatile("cp.async.wait_group 1;\n"); }

__device__ __forceinline__ float fsigmoid(float v) { return 1.f / (1.f + __expf(-v)); }

// ---------------- 0) weight prep ---------------------------------------------
__global__ void half_copy(const float* __restrict__ src, __half* __restrict__ dst, int n4) {
    int i = blockIdx.x * blockDim.x + threadIdx.x;
    if (i < n4) {
        float4 v = ((const float4*)src)[i];
        ((__half2*)dst)[i * 2]     = __floats2half2_rn(v.x, v.y);
        ((__half2*)dst)[i * 2 + 1] = __floats2half2_rn(v.z, v.w);
    }
}

// w2[kc][i][o] -> g_w2h[kc][p][i] (fp16), p = (o<512) ? 2o : 2(o-512)+1
__global__ void w2_perm_half(const float* __restrict__ w2) {
    __shared__ float tile[32][33];
    int kc = blockIdx.z;
    int i0 = blockIdx.x * 32;
    int o0 = blockIdx.y * 32;
    int tx = threadIdx.x, ty = threadIdx.y;   // 32 x 8
    #pragma unroll
    for (int r = 0; r < 32; r += 8)
        tile[ty + r][tx] = w2[((size_t)kc * C2 + (i0 + ty + r)) * C2 + o0 + tx];
    __syncthreads();
    #pragma unroll
    for (int r = 0; r < 32; r += 8) {
        int o = o0 + ty + r;
        int p = (o < CC) ? (2 * o) : (2 * (o - CC) + 1);
        g_w2h[((size_t)kc * C2 + p) * C2 + i0 + tx] = __float2half_rn(tile[tx][ty + r]);
    }
}

__global__ void b2_perm(const float* __restrict__ b2) {
    int p = blockIdx.x * blockDim.x + threadIdx.x;
    if (p < C2) {
        int ch = (p & 1) ? (CC + (p >> 1)) : (p >> 1);
        g_b2p[p] = b2[ch];
    }
}

// ---------------- 1) LayerNorm (stores fp16) ---------------------------------
__global__ void ln_kernel(const float* __restrict__ x,
                          const float* __restrict__ lg,
                          const float* __restrict__ lb) {
    int row = blockIdx.x;
    const float2* xin = (const float2*)(x + (size_t)row * CC);
    float2 v = xin[threadIdx.x];
    float s = v.x + v.y;
    float q = v.x * v.x + v.y * v.y;
    #pragma unroll
    for (int o = 16; o; o >>= 1) {
        s += __shfl_xor_sync(0xffffffffu, s, o);
        q += __shfl_xor_sync(0xffffffffu, q, o);
    }
    __shared__ float ss[8], sq[8];
    __shared__ float mu_s, rs_s;
    int w = threadIdx.x >> 5, l = threadIdx.x & 31;
    if (l == 0) { ss[w] = s; sq[w] = q; }
    __syncthreads();
    if (threadIdx.x == 0) {
        float S = 0.f, Q = 0.f;
        #pragma unroll
        for (int i = 0; i < 8; i++) { S += ss[i]; Q += sq[i]; }
        float mu = S * (1.f / CC);
        float var = Q * (1.f / CC) - mu * mu;
        mu_s = mu;
        rs_s = rsqrtf(var + 1e-5f);
    }
    __syncthreads();
    float mu = mu_s, rs = rs_s;
    int c = threadIdx.x * 2;
    float ox = (v.x - mu) * rs * lg[c]     + lb[c];
    float oy = (v.y - mu) * rs * lg[c + 1] + lb[c + 1];
    ((__half2*)(g_xnh + (size_t)row * CC))[threadIdx.x] = __floats2half2_rn(ox, oy);
}

// ---------------- 2/5) fp16 GEMM:  C = act(A @ W^T + bias) -------------------
// MODE 0: A = g_xnh -> g_h1h (SiLU, fp16 store). MODE 1: A = g_h2h -> out (fp32).
template <int N, int MODE, int KD>
__global__ __launch_bounds__(256, 2)
void gemm_h(const __half* __restrict__ W, const float* __restrict__ bias,
            float* __restrict__ outParam) {
    extern __shared__ float smf[];
    __half* smh = (__half*)smf;
    constexpr int ROWW = 40;          // halves per row (80 B; 20-word stride bank-bijective)
    constexpr int TSZ  = 128 * ROWW;
    __half* AsB = smh;
    __half* BsB = smh + 3 * TSZ;
    constexpr int KT = KD / 32;

    const __half* A = (MODE == 0) ? g_xnh : g_h2h;

    const int m0 = blockIdx.x * 128, n0 = blockIdx.y * 128;
    const int tid = threadIdx.x;
    const int lane = tid & 31, warp = tid >> 5;
    const int wm = warp & 1, wn = warp >> 1;
    const int g = lane >> 2, t = lane & 3;

    auto stage = [&](int s) {
        __half* a = AsB + (s % 3) * TSZ;
        __half* b = BsB + (s % 3) * TSZ;
        const __half* Ab = A + (size_t)m0 * KD + s * 32;
        const __half* Bb = W + (size_t)n0 * KD + s * 32;
        #pragma unroll
        for (int p = 0; p < 2; p++) {
            int c = tid * 2 + p;
            int row = c >> 2, kh = c & 3;
            uint32_t dA = (uint32_t)__cvta_generic_to_shared(a + row * ROWW + kh * 8);
            uint32_t dB = (uint32_t)__cvta_generic_to_shared(b + row * ROWW + kh * 8);
            cpa16(dA, Ab + (size_t)row * KD + kh * 8);
            cpa16(dB, Bb + (size_t)row * KD + kh * 8);
        }
        cp_commit();
    };

    float acc[4][4][4];
    #pragma unroll
    for (int mi = 0; mi < 4; mi++)
        #pragma unroll
        for (int ni = 0; ni < 4; ni++)
            #pragma unroll
            for (int j = 0; j < 4; j++) acc[mi][ni][j] = 0.f;

    auto comp = [&](int s) {
        const uint32_t* a = (const uint32_t*)(AsB + (s % 3) * TSZ);
        const uint32_t* b = (const uint32_t*)(BsB + (s % 3) * TSZ);
        #pragma unroll
        for (int ks = 0; ks < 2; ks++) {
            const int kb = ks * 8;
            uint32_t af[4][4];
            #pragma unroll
            for (int mi = 0; mi < 4; mi++) {
                int r0 = wm * 64 + mi * 16 + g;
                af[mi][0] = a[r0 * 20 + kb + t];
                af[mi][1] = a[(r0 + 8) * 20 + kb + t];
                af[mi][2] = a[r0 * 20 + kb + t + 4];
                af[mi][3] = a[(r0 + 8) * 20 + kb + t + 4];
            }
            uint32_t bf[4][2];
            #pragma unroll
            for (int ni = 0; ni < 4; ni++) {
                int c0 = wn * 32 + ni * 8 + g;
                bf[ni][0] = b[c0 * 20 + kb + t];
                bf[ni][1] = b[c0 * 20 + kb + t + 4];
            }
            #pragma unroll
            for (int mi = 0; mi < 4; mi++)
                #pragma unroll
                for (int ni = 0; ni < 4; ni++)
                    mma16h(acc[mi][ni], af[mi], bf[ni]);
        }
    };

    stage(0);
    stage(1);
    #pragma unroll 1
    for (int kt = 0; kt < KT; ++kt) {
        cp_wait1();
        __syncthreads();
        if (kt + 2 < KT) stage(kt + 2);
        comp(kt);
    }

    #pragma unroll
    for (int mi = 0; mi < 4; mi++) {
        int r0 = m0 + wm * 64 + mi * 16 + g;
        #pragma unroll
        for (int ni = 0; ni < 4; ni++) {
            int c0 = n0 + wn * 32 + ni * 8 + t * 2;
            float2 v0, v1;
            v0.x = acc[mi][ni][0] + bias[c0];
            v0.y = acc[mi][ni][1] + bias[c0 + 1];
            v1.x = acc[mi][ni][2] + bias[c0];
            v1.y = acc[mi][ni][3] + bias[c0 + 1];
            if (MODE == 0) {
                v0.x = v0.x * fsigmoid(v0.x); v0.y = v0.y * fsigmoid(v0.y);
                v1.x = v1.x * fsigmoid(v1.x); v1.y = v1.y * fsigmoid(v1.y);
                *(__half2*)(g_h1h + (size_t)r0 * N + c0)       = __floats2half2_rn(v0.x, v0.y);
                *(__half2*)(g_h1h + (size_t)(r0 + 8) * N + c0) = __floats2half2_rn(v1.x, v1.y);
            } else {
                *(float2*)(outParam + (size_t)r0 * N + c0)       = v0;
                *(float2*)(outParam + (size_t)(r0 + 8) * N + c0) = v1;
            }
        }
    }
}

// ---------------- 3) Conv1d (K=5) fp16 GEMM, A reused across taps ------------
// A tile: 136 rows (t0-2 .. t0+133) loaded ONCE per K-tile kt; the 5 taps read
// it with a row offset of kc. B ring: 3 stages as before. Fused GLU+BN epilogue.
__global__ __launch_bounds__(256, 2)
void conv_fp16(const float* __restrict__ bg, const float* __restrict__ bb_,
               const float* __restrict__ bm, const float* __restrict__ bv) {
    extern __shared__ float smf[];
    __half* smh = (__half*)smf;
    constexpr int ROWW = 40;
    constexpr int BTSZ = 128 * ROWW;          // B tile halves
    constexpr int AROWS = 136;
    constexpr int ATSZ = AROWS * ROWW;        // A tile halves
    __half* AsB = smh;                        // 2 x A tiles
    __half* BsB = smh + 2 * ATSZ;             // 3 x B tiles
    constexpr int NIT = 160;                  // 32 K-tiles x 5 taps

    const int m0 = blockIdx.x * 128, n0 = blockIdx.y * 128;
    const int bb = m0 >> 10, t0 = m0 & 1023;
    const int tid = threadIdx.x;
    const int lane = tid & 31, warp = tid >> 5;
    const int wm = warp & 1, wn = warp >> 1;
    const int g = lane >> 2, t = lane & 3;

    // Stage A tile for K-tile kt: rows r=0..135 -> trow = t0 + r - 2
    auto stageA = [&](int kt) {
        __half* a = AsB + (kt & 1) * ATSZ;
        const __half* Ab = g_h1h + (size_t)(bb * TT) * C2 + kt * 32;
        #pragma unroll
        for (int p = 0; p < 2; p++) {
            int c = tid + p * 256;            // chunks 0..511
            int row = c >> 2, kh = c & 3;
            uint32_t d = (uint32_t)__cvta_generic_to_shared(a + row * ROWW + kh * 8);
            int trow = t0 + row - 2;
            bool ok = (trow >= 0) && (trow < TT);
            cpa16p(d, Ab + (size_t)(ok ? trow : 0) * C2 + kh * 8, ok);
        }
        if (tid < 32) {                       // chunks 512..543 (rows 128..135)
            int c = tid + 512;
            int row = c >> 2, kh = c & 3;
            uint32_t d = (uint32_t)__cvta_generic_to_shared(a + row * ROWW + kh * 8);
            int trow = t0 + row - 2;
            bool ok = (trow >= 0) && (trow < TT);
            cpa16p(d, Ab + (size_t)(ok ? trow : 0) * C2 + kh * 8, ok);
        }
    };

    // Stage B tile for iteration s (kt = s/5, kc = s%5)
    auto stageB = [&](int s) {
        int kt = s / 5;
        int kc = s - kt * 5;
        __half* b = BsB + (s % 3) * BTSZ;
        const __half* Bb = g_w2h + ((size_t)kc * C2 + n0) * C2 + kt * 32;
        #pragma unroll
        for (int p = 0; p < 2; p++) {
            int c = tid * 2 + p;
            int row = c >> 2, kh = c & 3;
            uint32_t d = (uint32_t)__cvta_generic_to_shared(b + row * ROWW + kh * 8);
            cpa16(d, Bb + (size_t)row * C2 + kh * 8);
        }
    };

    float acc[4][4][4];
    #pragma unroll
    for (int mi = 0; mi < 4; mi++)
        #pragma unroll
        for (int ni = 0; ni < 4; ni++)
            #pragma unroll
            for (int j = 0; j < 4; j++) acc[mi][ni][j] = 0.f;

    auto comp = [&](int s) {
        int kt = s / 5;
        int kc = s - kt * 5;                  // A row offset for this tap
        const uint32_t* a = (const uint32_t*)(AsB + (kt & 1) * ATSZ);
        const uint32_t* b = (const uint32_t*)(BsB + (s % 3) * BTSZ);
        #pragma unroll
        for (int ks = 0; ks < 2; ks++) {
            const int kb = ks * 8;
            uint32_t af[4][4];
            #pragma unroll
            for (int mi = 0; mi < 4; mi++) {
                int r0 = wm * 64 + mi * 16 + g + kc;
                af[mi][0] = a[r0 * 20 + kb + t];
                af[mi][1] = a[(r0 + 8) * 20 + kb + t];
                af[mi][2] = a[r0 * 20 + kb + t + 4];
                af[mi][3] = a[(r0 + 8) * 20 + kb + t + 4];
            }
            uint32_t bf[4][2];
            #pragma unroll
            for (int ni = 0; ni < 4; ni++) {
                int c0 = wn * 32 + ni * 8 + g;
                bf[ni][0] = b[c0 * 20 + kb + t];
                bf[ni][1] = b[c0 * 20 + kb + t + 4];
            }
            #pragma unroll
            for (int mi = 0; mi < 4; mi++)
                #pragma unroll
                for (int ni = 0; ni < 4; ni++)
                    mma16h(acc[mi][ni], af[mi], bf[ni]);
        }
    };

    // Prologue: group0 = A(0), group1 = B(0), group2 = B(1)
    stageA(0); cp_commit();
    stageB(0); cp_commit();
    stageB(1); cp_commit();

    #pragma unroll 1
    for (int s = 0; s < NIT; ++s) {
        cp_wait1();            // B(s) (group s+1) and A(s/5) retired
        __syncthreads();
        // One commit group per iteration: B(s+2) (+ A(kt+1) when s%5==0)
        if (s % 5 == 0) {
            int ktn = s / 5 + 1;
            if (ktn < 32) stageA(ktn);
        }
        if (s + 2 < NIT) stageB(s + 2);
        cp_commit();
        comp(s);
    }

    // Fused epilogue: bias -> GLU -> BN -> fp16 -> g_h2h
    #pragma unroll
    for (int mi = 0; mi < 4; mi++) {
        int r0 = m0 + wm * 64 + mi * 16 + g;
        #pragma unroll
        for (int ni = 0; ni < 4; ni++) {
            int c0 = n0 + wn * 32 + ni * 8 + t * 2;
            int j  = c0 >> 1;
            float ba = g_b2p[c0], bgg = g_b2p[c0 + 1];
            float sc = bg[j] * rsqrtf(bv[j] + 1e-5f);
            float mean = bm[j], beta = bb_[j];
            float a0 = acc[mi][ni][0] + ba, g0 = acc[mi][ni][1] + bgg;
            float a1 = acc[mi][ni][2] + ba, g1 = acc[mi][ni][3] + bgg;
            float o0 = a0 * fsigmoid(g0);
            float o1 = a1 * fsigmoid(g1);
            g_h2h[(size_t)r0 * CC + j]       = __float2half_rn((o0 - mean) * sc + beta);
            g_h2h[(size_t)(r0 + 8) * CC + j] = __float2half_rn((o1 - mean) * sc + beta);
        }
    }
}

// ---------------- launch -----------------------------------------------------
extern "C" void kernel_launch(void* const* d_in, const int* in_sizes, int n_in,
                              void* d_out, int out_size) {
    const float* x     = (const float*)d_in[0];
    const float* ln_g  = (const float*)d_in[1];
    const float* ln_b  = (const float*)d_in[2];
    const float* w1    = (const float*)d_in[3];
    const float* b1    = (const float*)d_in[4];
    const float* w2    = (const float*)d_in[5];
    const float* b2    = (const float*)d_in[6];
    const float* bn_g  = (const float*)d_in[7];
    const float* bn_b  = (const float*)d_in[8];
    const float* bn_m  = (const float*)d_in[9];
    const float* bn_v  = (const float*)d_in[10];
    const float* w3    = (const float*)d_in[11];
    const float* b3    = (const float*)d_in[12];
    float* out = (float*)d_out;

    const int smem_gemm = 6 * 128 * 40 * 2;                        // 61440
    const int smem_conv = (2 * 136 * 40 + 3 * 128 * 40) * 2;       // 52480
    cudaFuncSetAttribute(gemm_h<C2, 0, CC>,
                         cudaFuncAttributeMaxDynamicSharedMemorySize, smem_gemm);
    cudaFuncSetAttribute(gemm_h<CC, 1, CC>,
                         cudaFuncAttributeMaxDynamicSharedMemorySize, smem_gemm);
    cudaFuncSetAttribute(conv_fp16,
                         cudaFuncAttributeMaxDynamicSharedMemorySize, smem_conv);

    __half *w1h, *w3h;
    cudaGetSymbolAddress((void**)&w1h, g_w1h);
    cudaGetSymbolAddress((void**)&w3h, g_w3h);

    half_copy<<<(C2 * CC / 4 + 255) / 256, 256>>>(w1, w1h, C2 * CC / 4);
    half_copy<<<(CC * CC / 4 + 255) / 256, 256>>>(w3, w3h, CC * CC / 4);
    w2_perm_half<<<dim3(C2 / 32, C2 / 32, 5), dim3(32, 8)>>>(w2);
    b2_perm<<<4, 256>>>(b2);

    ln_kernel<<<MTOT, 256>>>(x, ln_g, ln_b);
    gemm_h<C2, 0, CC><<<dim3(MTOT / 128, C2 / 128), 256, smem_gemm>>>(w1h, b1, nullptr);
    conv_fp16<<<dim3(MTOT / 128, C2 / 128), 256, smem_conv>>>(bn_g, bn_b, bn_m, bn_v);
    gemm_h<CC, 1, CC><<<dim3(MTOT / 128, CC / 128), 256, smem_gemm>>>(w3h, b3, out);
}

// round 14
// speedup vs baseline: 3.0294x; 1.1278x over previous
#include <cuda_runtime.h>
#include <cuda_fp16.h>
#include <cstdint>

// Problem constants
#define BQ   16
#define TT   1024
#define CC   512
#define MTOT (BQ * TT)      // 16384 rows (b,t)
#define C2   (2 * CC)       // 1024

// ---------------- scratch (device globals; no allocation allowed) -----------
__device__ __half g_xnh[(size_t)MTOT * CC];     // LN output (fp16)
__device__ __half g_h1h[(size_t)MTOT * C2];     // GEMM1+SiLU output (fp16)
__device__ __half g_h2h[(size_t)MTOT * CC];     // conv+GLU+BN output (fp16)
__device__ __half g_w1h[(size_t)C2 * CC];       // fp16 weights
__device__ __half g_w3h[(size_t)CC * CC];
__device__ __half g_w2h[(size_t)5 * C2 * C2];   // w2 permuted+transposed [kc][p][i], fp16
__device__ float  g_b2p[C2];                    // permuted conv bias

// ---------------- helpers ---------------------------------------------------
__device__ __forceinline__ void mma16h(float (&d)[4], const uint32_t (&a)[4], const uint32_t (&b)[2]) {
    asm volatile(
        "mma.sync.aligned.m16n8k16.row.col.f32.f16.f16.f32 "
        "{%0,%1,%2,%3}, {%4,%5,%6,%7}, {%8,%9}, {%0,%1,%2,%3};\n"
        : "+f"(d[0]), "+f"(d[1]), "+f"(d[2]), "+f"(d[3])
        : "r"(a[0]), "r"(a[1]), "r"(a[2]), "r"(a[3]),
          "r"(b[0]), "r"(b[1]));
}
__device__ __forceinline__ void ldsm4(uint32_t& r0, uint32_t& r1, uint32_t& r2, uint32_t& r3,
                                      uint32_t addr) {
    asm volatile("ldmatrix.sync.aligned.m8n8.x4.shared.b16 {%0,%1,%2,%3}, [%4];"
                 : "=r"(r0), "=r"(r1), "=r"(r2), "=r"(r3) : "r"(addr));
}

__device__ __forceinline__ void cpa16(uint32_t dst, const void* src) {
    asm volatile("cp.async.cg.shared.global [%0], [%1], 16;\n" :: "r"(dst), "l"(src));
}
__device__ __forceinline__ void cpa16p(uint32_t dst, const void* src, bool pred) {
    int sz = pred ? 16 : 0;
    asm volatile("cp.async.cg.shared.global [%0], [%1], 16, %2;\n" :: "r"(dst), "l"(src), "r"(sz));
}
__device__ __forceinline__ void cp_commit() { asm volatile("cp.async.commit_group;\n"); }
__device__ __forceinline__ void cp_wait1() { asm volatile("cp.async.wait_group 1;\n"); }

__device__ __forceinline__ float fsigmoid(float v) { return 1.f / (1.f + __expf(-v)); }

// ---------------- 0) weight prep (merged small preps) ------------------------
// i < 131072: w1 -> g_w1h ; i < 196608: w3 -> g_w3h ; i < 197632: b2 perm
__global__ void prep_small(const float* __restrict__ w1, const float* __restrict__ w3,
                           const float* __restrict__ b2) {
    int i = blockIdx.x * blockDim.x + threadIdx.x;
    if (i < 131072) {
        float4 v = ((const float4*)w1)[i];
        ((__half2*)g_w1h)[i * 2]     = __floats2half2_rn(v.x, v.y);
        ((__half2*)g_w1h)[i * 2 + 1] = __floats2half2_rn(v.z, v.w);
    } else if (i < 196608) {
        int j = i - 131072;                    // 65536 float4 = CC*CC/4
        float4 v = ((const float4*)w3)[j];
        ((__half2*)g_w3h)[j * 2]     = __floats2half2_rn(v.x, v.y);
        ((__half2*)g_w3h)[j * 2 + 1] = __floats2half2_rn(v.z, v.w);
    } else if (i < 197632) {
        int p = i - 196608;
        int ch = (p & 1) ? (CC + (p >> 1)) : (p >> 1);
        g_b2p[p] = b2[ch];
    }
}

// w2[kc][i][o] -> g_w2h[kc][p][i] (fp16), p = (o<512) ? 2o : 2(o-512)+1
__global__ void w2_perm_half(const float* __restrict__ w2) {
    __shared__ float tile[32][33];
    int kc = blockIdx.z;
    int i0 = blockIdx.x * 32;
    int o0 = blockIdx.y * 32;
    int tx = threadIdx.x, ty = threadIdx.y;   // 32 x 8
    #pragma unroll
    for (int r = 0; r < 32; r += 8)
        tile[ty + r][tx] = w2[((size_t)kc * C2 + (i0 + ty + r)) * C2 + o0 + tx];
    __syncthreads();
    #pragma unroll
    for (int r = 0; r < 32; r += 8) {
        int o = o0 + ty + r;
        int p = (o < CC) ? (2 * o) : (2 * (o - CC) + 1);
        g_w2h[((size_t)kc * C2 + p) * C2 + i0 + tx] = __float2half_rn(tile[tx][ty + r]);
    }
}

// ---------------- 1) LayerNorm (stores fp16) ---------------------------------
__global__ void ln_kernel(const float* __restrict__ x,
                          const float* __restrict__ lg,
                          const float* __restrict__ lb) {
    int row = blockIdx.x;
    const float2* xin = (const float2*)(x + (size_t)row * CC);
    float2 v = xin[threadIdx.x];
    float s = v.x + v.y;
    float q = v.x * v.x + v.y * v.y;
    #pragma unroll
    for (int o = 16; o; o >>= 1) {
        s += __shfl_xor_sync(0xffffffffu, s, o);
        q += __shfl_xor_sync(0xffffffffu, q, o);
    }
    __shared__ float ss[8], sq[8];
    __shared__ float mu_s, rs_s;
    int w = threadIdx.x >> 5, l = threadIdx.x & 31;
    if (l == 0) { ss[w] = s; sq[w] = q; }
    __syncthreads();
    if (threadIdx.x == 0) {
        float S = 0.f, Q = 0.f;
        #pragma unroll
        for (int i = 0; i < 8; i++) { S += ss[i]; Q += sq[i]; }
        float mu = S * (1.f / CC);
        float var = Q * (1.f / CC) - mu * mu;
        mu_s = mu;
        rs_s = rsqrtf(var + 1e-5f);
    }
    __syncthreads();
    float mu = mu_s, rs = rs_s;
    int c = threadIdx.x * 2;
    float ox = (v.x - mu) * rs * lg[c]     + lb[c];
    float oy = (v.y - mu) * rs * lg[c + 1] + lb[c + 1];
    ((__half2*)(g_xnh + (size_t)row * CC))[threadIdx.x] = __floats2half2_rn(ox, oy);
}

// ---------------- 2/5) fp16 GEMM with ldmatrix fragments ---------------------
// MODE 0: A = g_xnh -> g_h1h (SiLU, fp16 store). MODE 1: A = g_h2h -> out (fp32).
template <int N, int MODE, int KD>
__global__ __launch_bounds__(256, 2)
void gemm_h(const __half* __restrict__ W, const float* __restrict__ bias,
            float* __restrict__ outParam) {
    extern __shared__ float smf[];
    __half* smh = (__half*)smf;
    constexpr int ROWW = 40;          // halves per row (80 B; bank-bijective, LDSM-safe)
    constexpr int TSZ  = 128 * ROWW;
    __half* AsB = smh;
    __half* BsB = smh + 3 * TSZ;
    constexpr int KT = KD / 32;

    const __half* A = (MODE == 0) ? g_xnh : g_h2h;

    const int m0 = blockIdx.x * 128, n0 = blockIdx.y * 128;
    const int tid = threadIdx.x;
    const int lane = tid & 31, warp = tid >> 5;
    const int wm = warp & 1, wn = warp >> 1;
    const int g = lane >> 2, t = lane & 3;
    const int sub = lane >> 3, lr = lane & 7;
    // ldmatrix per-lane offsets (bytes): A (m0/m1 rows, m2/m3 +8 cols), B (m0/m1 k-halves, m2/m3 +8 rows)
    const uint32_t aoff = (((sub & 1) * 8 + lr) * ROWW + (sub >> 1) * 8) * 2;
    const uint32_t boff = (((sub >> 1) * 8 + lr) * ROWW + (sub & 1) * 8) * 2;

    auto stage = [&](int s) {
        __half* a = AsB + (s % 3) * TSZ;
        __half* b = BsB + (s % 3) * TSZ;
        const __half* Ab = A + (size_t)m0 * KD + s * 32;
        const __half* Bb = W + (size_t)n0 * KD + s * 32;
        #pragma unroll
        for (int p = 0; p < 2; p++) {
            int c = tid * 2 + p;
            int row = c >> 2, kh = c & 3;
            uint32_t dA = (uint32_t)__cvta_generic_to_shared(a + row * ROWW + kh * 8);
            uint32_t dB = (uint32_t)__cvta_generic_to_shared(b + row * ROWW + kh * 8);
            cpa16(dA, Ab + (size_t)row * KD + kh * 8);
            cpa16(dB, Bb + (size_t)row * KD + kh * 8);
        }
        cp_commit();
    };

    float acc[4][4][4];
    #pragma unroll
    for (int mi = 0; mi < 4; mi++)
        #pragma unroll
        for (int ni = 0; ni < 4; ni++)
            #pragma unroll
            for (int j = 0; j < 4; j++) acc[mi][ni][j] = 0.f;

    auto comp = [&](int s) {
        uint32_t abase = (uint32_t)__cvta_generic_to_shared(AsB + (s % 3) * TSZ) + aoff;
        uint32_t bbase = (uint32_t)__cvta_generic_to_shared(BsB + (s % 3) * TSZ) + boff;
        #pragma unroll
        for (int ks = 0; ks < 2; ks++) {
            uint32_t af[4][4];
            #pragma unroll
            for (int mi = 0; mi < 4; mi++)
                ldsm4(af[mi][0], af[mi][1], af[mi][2], af[mi][3],
                      abase + (wm * 64 + mi * 16) * (ROWW * 2) + ks * 32);
            uint32_t bf[4][2];
            #pragma unroll
            for (int np = 0; np < 2; np++)
                ldsm4(bf[2 * np][0], bf[2 * np][1], bf[2 * np + 1][0], bf[2 * np + 1][1],
                      bbase + (wn * 32 + np * 16) * (ROWW * 2) + ks * 32);
            #pragma unroll
            for (int mi = 0; mi < 4; mi++)
                #pragma unroll
                for (int ni = 0; ni < 4; ni++)
                    mma16h(acc[mi][ni], af[mi], bf[ni]);
        }
    };

    stage(0);
    stage(1);
    #pragma unroll 1
    for (int kt = 0; kt < KT; ++kt) {
        cp_wait1();
        __syncthreads();
        if (kt + 2 < KT) stage(kt + 2);
        comp(kt);
    }

    #pragma unroll
    for (int mi = 0; mi < 4; mi++) {
        int r0 = m0 + wm * 64 + mi * 16 + g;
        #pragma unroll
        for (int ni = 0; ni < 4; ni++) {
            int c0 = n0 + wn * 32 + ni * 8 + t * 2;
            float2 v0, v1;
            v0.x = acc[mi][ni][0] + bias[c0];
            v0.y = acc[mi][ni][1] + bias[c0 + 1];
            v1.x = acc[mi][ni][2] + bias[c0];
            v1.y = acc[mi][ni][3] + bias[c0 + 1];
            if (MODE == 0) {
                v0.x = v0.x * fsigmoid(v0.x); v0.y = v0.y * fsigmoid(v0.y);
                v1.x = v1.x * fsigmoid(v1.x); v1.y = v1.y * fsigmoid(v1.y);
                *(__half2*)(g_h1h + (size_t)r0 * N + c0)       = __floats2half2_rn(v0.x, v0.y);
                *(__half2*)(g_h1h + (size_t)(r0 + 8) * N + c0) = __floats2half2_rn(v1.x, v1.y);
            } else {
                *(float2*)(outParam + (size_t)r0 * N + c0)       = v0;
                *(float2*)(outParam + (size_t)(r0 + 8) * N + c0) = v1;
            }
        }
    }
}

// ---------------- 3) Conv1d (K=5), A reused across taps, ldmatrix ------------
__global__ __launch_bounds__(256, 2)
void conv_fp16(const float* __restrict__ bg, const float* __restrict__ bb_,
               const float* __restrict__ bm, const float* __restrict__ bv) {
    extern __shared__ float smf[];
    __half* smh = (__half*)smf;
    constexpr int ROWW = 40;
    constexpr int BTSZ = 128 * ROWW;
    constexpr int AROWS = 136;
    constexpr int ATSZ = AROWS * ROWW;
    __half* AsB = smh;                        // 2 x A tiles
    __half* BsB = smh + 2 * ATSZ;             // 3 x B tiles
    constexpr int NIT = 160;

    const int m0 = blockIdx.x * 128, n0 = blockIdx.y * 128;
    const int bb = m0 >> 10, t0 = m0 & 1023;
    const int tid = threadIdx.x;
    const int lane = tid & 31, warp = tid >> 5;
    const int wm = warp & 1, wn = warp >> 1;
    const int g = lane >> 2, t = lane & 3;
    const int sub = lane >> 3, lr = lane & 7;
    const uint32_t aoff = (((sub & 1) * 8 + lr) * ROWW + (sub >> 1) * 8) * 2;
    const uint32_t boff = (((sub >> 1) * 8 + lr) * ROWW + (sub & 1) * 8) * 2;

    auto stageA = [&](int kt) {
        __half* a = AsB + (kt & 1) * ATSZ;
        const __half* Ab = g_h1h + (size_t)(bb * TT) * C2 + kt * 32;
        #pragma unroll
        for (int p = 0; p < 2; p++) {
            int c = tid + p * 256;
            int row = c >> 2, kh = c & 3;
            uint32_t d = (uint32_t)__cvta_generic_to_shared(a + row * ROWW + kh * 8);
            int trow = t0 + row - 2;
            bool ok = (trow >= 0) && (trow < TT);
            cpa16p(d, Ab + (size_t)(ok ? trow : 0) * C2 + kh * 8, ok);
        }
        if (tid < 32) {
            int c = tid + 512;
            int row = c >> 2, kh = c & 3;
            uint32_t d = (uint32_t)__cvta_generic_to_shared(a + row * ROWW + kh * 8);
            int trow = t0 + row - 2;
            bool ok = (trow >= 0) && (trow < TT);
            cpa16p(d, Ab + (size_t)(ok ? trow : 0) * C2 + kh * 8, ok);
        }
    };

    auto stageB = [&](int s) {
        int kt = s / 5;
        int kc = s - kt * 5;
        __half* b = BsB + (s % 3) * BTSZ;
        const __half* Bb = g_w2h + ((size_t)kc * C2 + n0) * C2 + kt * 32;
        #pragma unroll
        for (int p = 0; p < 2; p++) {
            int c = tid * 2 + p;
            int row = c >> 2, kh = c & 3;
            uint32_t d = (uint32_t)__cvta_generic_to_shared(b + row * ROWW + kh * 8);
            cpa16(d, Bb + (size_t)row * C2 + kh * 8);
        }
    };

    float acc[4][4][4];
    #pragma unroll
    for (int mi = 0; mi < 4; mi++)
        #pragma unroll
        for (int ni = 0; ni < 4; ni++)
            #pragma unroll
            for (int j = 0; j < 4; j++) acc[mi][ni][j] = 0.f;

    auto comp = [&](int s) {
        int kt = s / 5;
        int kc = s - kt * 5;
        uint32_t abase = (uint32_t)__cvta_generic_to_shared(AsB + (kt & 1) * ATSZ)
                       + kc * (ROWW * 2) + aoff;
        uint32_t bbase = (uint32_t)__cvta_generic_to_shared(BsB + (s % 3) * BTSZ) + boff;
        #pragma unroll
        for (int ks = 0; ks < 2; ks++) {
            uint32_t af[4][4];
            #pragma unroll
            for (int mi = 0; mi < 4; mi++)
                ldsm4(af[mi][0], af[mi][1], af[mi][2], af[mi][3],
                      abase + (wm * 64 + mi * 16) * (ROWW * 2) + ks * 32);
            uint32_t bf[4][2];
            #pragma unroll
            for (int np = 0; np < 2; np++)
                ldsm4(bf[2 * np][0], bf[2 * np][1], bf[2 * np + 1][0], bf[2 * np + 1][1],
                      bbase + (wn * 32 + np * 16) * (ROWW * 2) + ks * 32);
            #pragma unroll
            for (int mi = 0; mi < 4; mi++)
                #pragma unroll
                for (int ni = 0; ni < 4; ni++)
                    mma16h(acc[mi][ni], af[mi], bf[ni]);
        }
    };

    // Prologue: group0 = A(0), group1 = B(0), group2 = B(1)
    stageA(0); cp_commit();
    stageB(0); cp_commit();
    stageB(1); cp_commit();

    #pragma unroll 1
    for (int s = 0; s < NIT; ++s) {
        cp_wait1();
        __syncthreads();
        if (s % 5 == 0) {
            int ktn = s / 5 + 1;
            if (ktn < 32) stageA(ktn);
        }
        if (s + 2 < NIT) stageB(s + 2);
        cp_commit();
        comp(s);
    }

    // Fused epilogue: bias -> GLU -> BN -> fp16 -> g_h2h
    #pragma unroll
    for (int mi = 0; mi < 4; mi++) {
        int r0 = m0 + wm * 64 + mi * 16 + g;
        #pragma unroll
        for (int ni = 0; ni < 4; ni++) {
            int c0 = n0 + wn * 32 + ni * 8 + t * 2;
            int j  = c0 >> 1;
            float ba = g_b2p[c0], bgg = g_b2p[c0 + 1];
            float sc = bg[j] * rsqrtf(bv[j] + 1e-5f);
            float mean = bm[j], beta = bb_[j];
            float a0 = acc[mi][ni][0] + ba, g0 = acc[mi][ni][1] + bgg;
            float a1 = acc[mi][ni][2] + ba, g1 = acc[mi][ni][3] + bgg;
            float o0 = a0 * fsigmoid(g0);
            float o1 = a1 * fsigmoid(g1);
            g_h2h[(size_t)r0 * CC + j]       = __float2half_rn((o0 - mean) * sc + beta);
            g_h2h[(size_t)(r0 + 8) * CC + j] = __float2half_rn((o1 - mean) * sc + beta);
        }
    }
}

// ---------------- launch -----------------------------------------------------
extern "C" void kernel_launch(void* const* d_in, const int* in_sizes, int n_in,
                              void* d_out, int out_size) {
    const float* x     = (const float*)d_in[0];
    const float* ln_g  = (const float*)d_in[1];
    const float* ln_b  = (const float*)d_in[2];
    const float* w1    = (const float*)d_in[3];
    const float* b1    = (const float*)d_in[4];
    const float* w2    = (const float*)d_in[5];
    const float* b2    = (const float*)d_in[6];
    const float* bn_g  = (const float*)d_in[7];
    const float* bn_b  = (const float*)d_in[8];
    const float* bn_m  = (const float*)d_in[9];
    const float* bn_v  = (const float*)d_in[10];
    const float* w3    = (const float*)d_in[11];
    const float* b3    = (const float*)d_in[12];
    float* out = (float*)d_out;

    const int smem_gemm = 6 * 128 * 40 * 2;                        // 61440
    const int smem_conv = (2 * 136 * 40 + 3 * 128 * 40) * 2;       // 52480
    cudaFuncSetAttribute(gemm_h<C2, 0, CC>,
                         cudaFuncAttributeMaxDynamicSharedMemorySize, smem_gemm);
    cudaFuncSetAttribute(gemm_h<CC, 1, CC>,
                         cudaFuncAttributeMaxDynamicSharedMemorySize, smem_gemm);
    cudaFuncSetAttribute(conv_fp16,
                         cudaFuncAttributeMaxDynamicSharedMemorySize, smem_conv);

    // Device addresses of __device__ weight buffers (host shadow is NOT valid!)
    __half *w1h, *w3h;
    cudaGetSymbolAddress((void**)&w1h, g_w1h);
    cudaGetSymbolAddress((void**)&w3h, g_w3h);

    prep_small<<<(197632 + 255) / 256, 256>>>(w1, w3, b2);
    w2_perm_half<<<dim3(C2 / 32, C2 / 32, 5), dim3(32, 8)>>>(w2);

    ln_kernel<<<MTOT, 256>>>(x, ln_g, ln_b);
    gemm_h<C2, 0, CC><<<dim3(MTOT / 128, C2 / 128), 256, smem_gemm>>>(w1h, b1, nullptr);
    conv_fp16<<<dim3(MTOT / 128, C2 / 128), 256, smem_conv>>>(bn_g, bn_b, bn_m, bn_v);
    gemm_h<CC, 1, CC><<<dim3(MTOT / 128, CC / 128), 256, smem_gemm>>>(w3h, b3, out);
}